// round 1
// baseline (speedup 1.0000x reference)
#include <cuda_runtime.h>

// Problem constants
#define HH    64      // LSTM hidden size
#define TT    32      // timesteps
#define BB    4096    // batch
#define AA    6       // action dim
#define BROWS 64      // batch rows per CTA in lstm kernel
#define GATES 256     // 4*H
#define HSTR  68      // padded row stride for h in smem (floats)

// dynamic smem layout for lstm kernel (floats)
#define SM_WS (64 * 256)        // whh transposed+permuted: ws[k][u*4+t]
#define SM_H  (BROWS * HSTR)    // h state [row][unit]
#define SM_X  (BROWS * TT)      // x tile [row][t]
#define SMEM_FLOATS (SM_WS + SM_H + SM_X)
#define SMEM_BYTES (SMEM_FLOATS * 4)

// scratch: final hidden states for the two branches, [B][192] (3 LSTM outputs)
__device__ float g_hq[BB * 192];
__device__ float g_hi[BB * 192];

__device__ __forceinline__ float sigf(float x) {
    return __fdividef(1.f, 1.f + __expf(-x));
}
__device__ __forceinline__ float tanhf_(float x) {
    // accurate tanh via exp: 1 - 2/(e^{2x}+1); saturates correctly at +-1
    return 1.f - __fdividef(2.f, __expf(2.f * x) + 1.f);
}

// One CTA = (64 batch rows) x (one LSTM run). Gate columns are permuted so
// column p = u*4 + t (t: 0=i,1=f,2=g,3=o). Thread (gi in [0,32), ri in [0,8))
// owns rows ri*8..ri*8+7 and permuted gates gi*8..gi*8+7, i.e. hidden units
// {gi*2, gi*2+1} with all four gate types -> c state stays in registers.
__global__ __launch_bounds__(256) void lstm_kernel(
    const float* __restrict__ x0, const float* __restrict__ x1, const float* __restrict__ x2,
    const float* __restrict__ q00_wih, const float* __restrict__ q00_whh, const float* __restrict__ q00_b,
    const float* __restrict__ q01_wih, const float* __restrict__ q01_whh, const float* __restrict__ q01_b,
    const float* __restrict__ i00_wih, const float* __restrict__ i00_whh, const float* __restrict__ i00_b,
    const float* __restrict__ i01_wih, const float* __restrict__ i01_whh, const float* __restrict__ i01_b,
    const float* __restrict__ i02_wih, const float* __restrict__ i02_whh, const float* __restrict__ i02_b)
{
    extern __shared__ float smem[];
    float* ws  = smem;               // [64][256]  ws[k*256 + p]
    float* hsm = smem + SM_WS;       // [BROWS][HSTR]  h[row][unit]
    float* xs  = hsm + SM_H;         // [BROWS][TT]

    const float* x; const float* wih; const float* whh; const float* bias;
    float* hout; int coloff;
    switch (blockIdx.y) {
        case 0:  x = x0; wih = q00_wih; whh = q00_whh; bias = q00_b; hout = g_hq; coloff = 0;   break;
        case 1:  x = x1; wih = q01_wih; whh = q01_whh; bias = q01_b; hout = g_hq; coloff = 64;  break;
        case 2:  x = x2; wih = q01_wih; whh = q01_whh; bias = q01_b; hout = g_hq; coloff = 128; break;
        case 3:  x = x0; wih = i00_wih; whh = i00_whh; bias = i00_b; hout = g_hi; coloff = 0;   break;
        case 4:  x = x1; wih = i01_wih; whh = i01_whh; bias = i01_b; hout = g_hi; coloff = 64;  break;
        default: x = x2; wih = i02_wih; whh = i02_whh; bias = i02_b; hout = g_hi; coloff = 128; break;
    }

    const int tid = threadIdx.x;
    const int gi = tid & 31;
    const int ri = tid >> 5;
    const int r0 = blockIdx.x * BROWS;

    // load whh transposed + gate-permuted: ws[k][u*4+t] = whh[t*64+u][k]
    for (int idx = tid; idx < 64 * 256; idx += 256) {
        int go = idx >> 6;          // original gate row
        int k  = idx & 63;
        int t  = go >> 6;           // gate type 0..3
        int u  = go & 63;           // hidden unit
        ws[k * 256 + u * 4 + t] = whh[idx];
    }
    // x tile (coalesced: x is [B][T] contiguous)
    for (int idx = tid; idx < BROWS * TT; idx += 256)
        xs[idx] = x[r0 * TT + idx];
    // zero h state
    for (int idx = tid; idx < SM_H; idx += 256)
        hsm[idx] = 0.f;

    // per-thread gate constants (bias + wih, input dim is 1)
    float bfr[8], wifr[8];
    #pragma unroll
    for (int j = 0; j < 8; ++j) {
        int go = (j & 3) * 64 + gi * 2 + (j >> 2);   // original gate index
        bfr[j]  = bias[go];
        wifr[j] = wih[go];
    }
    float c[16];
    #pragma unroll
    for (int i = 0; i < 16; ++i) c[i] = 0.f;

    __syncthreads();

    const int gbase = gi * 8;
    for (int t = 0; t < TT; ++t) {
        float acc[8][8];
        #pragma unroll
        for (int r = 0; r < 8; ++r) {
            float xv = xs[(ri * 8 + r) * TT + t];
            #pragma unroll
            for (int j = 0; j < 8; ++j)
                acc[r][j] = fmaf(xv, wifr[j], bfr[j]);
        }
        if (t > 0) {
            #pragma unroll 4
            for (int k = 0; k < HH; ++k) {
                float4 wa = *(const float4*)&ws[k * 256 + gbase];
                float4 wb = *(const float4*)&ws[k * 256 + gbase + 4];
                #pragma unroll
                for (int r = 0; r < 8; ++r) {
                    float hv = hsm[(ri * 8 + r) * HSTR + k];   // warp-broadcast
                    acc[r][0] = fmaf(hv, wa.x, acc[r][0]);
                    acc[r][1] = fmaf(hv, wa.y, acc[r][1]);
                    acc[r][2] = fmaf(hv, wa.z, acc[r][2]);
                    acc[r][3] = fmaf(hv, wa.w, acc[r][3]);
                    acc[r][4] = fmaf(hv, wb.x, acc[r][4]);
                    acc[r][5] = fmaf(hv, wb.y, acc[r][5]);
                    acc[r][6] = fmaf(hv, wb.z, acc[r][6]);
                    acc[r][7] = fmaf(hv, wb.w, acc[r][7]);
                }
            }
        }
        // elementwise LSTM cell (c in registers)
        float hnew[8][2];
        #pragma unroll
        for (int r = 0; r < 8; ++r) {
            #pragma unroll
            for (int u = 0; u < 2; ++u) {
                float iv = acc[r][u * 4 + 0];
                float fv = acc[r][u * 4 + 1];
                float gv = acc[r][u * 4 + 2];
                float ov = acc[r][u * 4 + 3];
                float cc = sigf(fv) * c[r * 2 + u] + sigf(iv) * tanhf_(gv);
                c[r * 2 + u] = cc;
                hnew[r][u] = sigf(ov) * tanhf_(cc);
            }
        }
        __syncthreads();   // all reads of old h done
        if (t == TT - 1) {
            #pragma unroll
            for (int r = 0; r < 8; ++r) {
                int row = r0 + ri * 8 + r;
                hout[row * 192 + coloff + gi * 2 + 0] = hnew[r][0];
                hout[row * 192 + coloff + gi * 2 + 1] = hnew[r][1];
            }
        } else {
            #pragma unroll
            for (int r = 0; r < 8; ++r)
                *(float2*)&hsm[(ri * 8 + r) * HSTR + gi * 2] =
                    make_float2(hnew[r][0], hnew[r][1]);
            __syncthreads();  // new h visible
        }
    }
}

// Head: one warp per batch row. buf holds the 256-wide concat vector.
__global__ __launch_bounds__(256) void head_kernel(
    const float* __restrict__ s2,
    const float* __restrict__ q03_w, const float* __restrict__ q03_b,
    const float* __restrict__ q1_w,  const float* __restrict__ q1_b,
    const float* __restrict__ q2_w,  const float* __restrict__ q2_b,
    const float* __restrict__ i03_w, const float* __restrict__ i03_b,
    const float* __restrict__ i1_w,  const float* __restrict__ i1_b,
    const float* __restrict__ i2_w,  const float* __restrict__ i2_b,
    float* __restrict__ out)
{
    __shared__ float buf[8][260];
    const int w    = threadIdx.x >> 5;
    const int lane = threadIdx.x & 31;
    const int row  = blockIdx.x * 8 + w;

    const float s0  = s2[row * 3 + 0];
    const float s1v = s2[row * 3 + 1];
    const float s2v = s2[row * 3 + 2];

    #pragma unroll
    for (int br = 0; br < 2; ++br) {
        const float* gh  = br ? g_hi  : g_hq;
        const float* w03 = br ? i03_w : q03_w;
        const float* b03 = br ? i03_b : q03_b;
        const float* w1  = br ? i1_w  : q1_w;
        const float* b1  = br ? i1_b  : q1_b;

        __syncwarp();
        for (int k = lane; k < 192; k += 32)
            buf[w][k] = gh[row * 192 + k];
        for (int u = lane; u < 64; u += 32) {
            float a = b03[u] + s0 * w03[u * 3] + s1v * w03[u * 3 + 1] + s2v * w03[u * 3 + 2];
            buf[w][192 + u] = fmaxf(a, 0.f);
        }
        __syncwarp();

        float qv[2];
        #pragma unroll
        for (int uu = 0; uu < 2; ++uu) {
            int u = lane + uu * 32;
            float acc = b1[u];
            #pragma unroll 4
            for (int k = 0; k < 256; k += 4) {
                float4 wv = *(const float4*)&w1[u * 256 + k];
                acc = fmaf(wv.x, buf[w][k],     acc);
                acc = fmaf(wv.y, buf[w][k + 1], acc);
                acc = fmaf(wv.z, buf[w][k + 2], acc);
                acc = fmaf(wv.w, buf[w][k + 3], acc);
            }
            qv[uu] = fmaxf(acc, 0.f);
        }
        __syncwarp();
        buf[w][lane]      = qv[0];
        buf[w][lane + 32] = qv[1];
        __syncwarp();

        if (br == 0) {
            if (lane < AA) {
                float acc = q2_b[lane];
                #pragma unroll
                for (int u = 0; u < 64; ++u)
                    acc = fmaf(q2_w[lane * 64 + u], buf[w][u], acc);
                out[row * AA + lane] = acc;   // q output (no relu)
            }
        } else {
            if (lane < AA) {
                float acc = i2_b[lane];
                #pragma unroll
                for (int u = 0; u < 64; ++u)
                    acc = fmaf(i2_w[lane * 64 + u], buf[w][u], acc);
                buf[w][128 + lane] = fmaxf(acc, 0.f);   // i vector
            }
            __syncwarp();
            if (lane < AA) {
                float m = buf[w][128];
                #pragma unroll
                for (int j = 1; j < AA; ++j) m = fmaxf(m, buf[w][128 + j]);
                float s = 0.f;
                #pragma unroll
                for (int j = 0; j < AA; ++j) s += __expf(buf[w][128 + j] - m);
                float lse = m + __logf(s);
                float iv = buf[w][128 + lane];
                out[BB * AA + row * AA + lane]     = iv - lse;   // log_softmax(i)
                out[2 * BB * AA + row * AA + lane] = iv;         // i
            }
        }
    }
}

extern "C" void kernel_launch(void* const* d_in, const int* in_sizes, int n_in,
                              void* d_out, int out_size)
{
    const float* x0 = (const float*)d_in[0];
    const float* x1 = (const float*)d_in[1];
    const float* x2 = (const float*)d_in[2];
    const float* s2 = (const float*)d_in[3];
    const float* q00_wih = (const float*)d_in[4];
    const float* q00_whh = (const float*)d_in[5];
    const float* q00_b   = (const float*)d_in[6];
    const float* q01_wih = (const float*)d_in[7];
    const float* q01_whh = (const float*)d_in[8];
    const float* q01_b   = (const float*)d_in[9];
    const float* i00_wih = (const float*)d_in[10];
    const float* i00_whh = (const float*)d_in[11];
    const float* i00_b   = (const float*)d_in[12];
    const float* i01_wih = (const float*)d_in[13];
    const float* i01_whh = (const float*)d_in[14];
    const float* i01_b   = (const float*)d_in[15];
    const float* i02_wih = (const float*)d_in[16];
    const float* i02_whh = (const float*)d_in[17];
    const float* i02_b   = (const float*)d_in[18];
    const float* q03_w = (const float*)d_in[19];
    const float* q03_b = (const float*)d_in[20];
    const float* q1_w  = (const float*)d_in[21];
    const float* q1_b  = (const float*)d_in[22];
    const float* q2_w  = (const float*)d_in[23];
    const float* q2_b  = (const float*)d_in[24];
    const float* i03_w = (const float*)d_in[25];
    const float* i03_b = (const float*)d_in[26];
    const float* i1_w  = (const float*)d_in[27];
    const float* i1_b  = (const float*)d_in[28];
    const float* i2_w  = (const float*)d_in[29];
    const float* i2_b  = (const float*)d_in[30];
    float* out = (float*)d_out;

    cudaFuncSetAttribute(lstm_kernel, cudaFuncAttributeMaxDynamicSharedMemorySize, SMEM_BYTES);

    dim3 grid(BB / BROWS, 6);   // 64 batch tiles x 6 LSTM runs
    lstm_kernel<<<grid, 256, SMEM_BYTES>>>(
        x0, x1, x2,
        q00_wih, q00_whh, q00_b,
        q01_wih, q01_whh, q01_b,
        i00_wih, i00_whh, i00_b,
        i01_wih, i01_whh, i01_b,
        i02_wih, i02_whh, i02_b);

    head_kernel<<<BB / 8, 256>>>(
        s2,
        q03_w, q03_b, q1_w, q1_b, q2_w, q2_b,
        i03_w, i03_b, i1_w, i1_b, i2_w, i2_b,
        out);
}

// round 2
// speedup vs baseline: 1.0002x; 1.0002x over previous
#include <cuda_runtime.h>

// Problem constants
#define HH    64      // LSTM hidden size
#define TT    32      // timesteps
#define BB    4096    // batch
#define AA    6       // action dim
#define BROWS 64      // batch rows per CTA in lstm kernel
#define HSTR2 66      // padded row stride for duplicated h in smem (ull units)

typedef unsigned long long ull;

// smem layout for lstm kernel (bytes):
//   ws  floats [64][256]            : 65536
//   h2  ull    [BROWS][HSTR2]       : 33792   (each entry = {h,h} packed f32x2)
//   xs  floats [BROWS][TT]          : 8192
#define WS_FLOATS   (64 * 256)
#define H2_ULLS     (BROWS * HSTR2)
#define XS_FLOATS   (BROWS * TT)
#define LSTM_SMEM_BYTES (WS_FLOATS * 4 + H2_ULLS * 8 + XS_FLOATS * 4)

// head kernel smem (floats): wt[256][66] + buf[64][260] + qb[64][66] + ib[64][8]
#define WT_STR 66
#define BUF_STR 260
#define QB_STR 66
#define HEAD_SMEM_FLOATS (256 * WT_STR + 64 * BUF_STR + 64 * QB_STR + 64 * 8)
#define HEAD_SMEM_BYTES (HEAD_SMEM_FLOATS * 4)

// scratch: final hidden states for the two branches, [B][192] (3 LSTM outputs)
__device__ float g_hq[BB * 192];
__device__ float g_hi[BB * 192];

__device__ __forceinline__ float sigf(float x) {
    return __fdividef(1.f, 1.f + __expf(-x));
}
__device__ __forceinline__ float tanhf_(float x) {
    return 1.f - __fdividef(2.f, __expf(2.f * x) + 1.f);
}

__device__ __forceinline__ ull pack2(float lo, float hi) {
    ull r;
    asm("mov.b64 %0, {%1, %2};" : "=l"(r) : "f"(lo), "f"(hi));
    return r;
}
__device__ __forceinline__ void unpack2(ull v, float& lo, float& hi) {
    asm("mov.b64 {%0, %1}, %2;" : "=f"(lo), "=f"(hi) : "l"(v));
}
__device__ __forceinline__ ull ffma2(ull a, ull b, ull c) {
    ull d;
    asm("fma.rn.f32x2 %0, %1, %2, %3;" : "=l"(d) : "l"(a), "l"(b), "l"(c));
    return d;
}

// One CTA = (64 batch rows) x (one LSTM run). Gate columns permuted so column
// p = u*4 + t (t: 0=i,1=f,2=g,3=o). Thread (gi in [0,32), ri in [0,8)) owns
// rows ri*8..ri*8+7 and permuted columns gi*8..gi*8+7 = hidden units
// {gi*2, gi*2+1} with all four gates -> c state in registers.
// Recurrent matmul uses packed fma.rn.f32x2: gate pairs packed in 64-bit regs,
// h stored in smem pre-duplicated {h,h} so no per-k packing is needed.
__global__ __launch_bounds__(256, 2) void lstm_kernel(
    const float* __restrict__ x0, const float* __restrict__ x1, const float* __restrict__ x2,
    const float* __restrict__ q00_wih, const float* __restrict__ q00_whh, const float* __restrict__ q00_b,
    const float* __restrict__ q01_wih, const float* __restrict__ q01_whh, const float* __restrict__ q01_b,
    const float* __restrict__ i00_wih, const float* __restrict__ i00_whh, const float* __restrict__ i00_b,
    const float* __restrict__ i01_wih, const float* __restrict__ i01_whh, const float* __restrict__ i01_b,
    const float* __restrict__ i02_wih, const float* __restrict__ i02_whh, const float* __restrict__ i02_b)
{
    extern __shared__ char smem_raw[];
    float* ws = (float*)smem_raw;                        // [64][256]
    ull*   h2 = (ull*)(smem_raw + WS_FLOATS * 4);        // [BROWS][HSTR2]
    float* xs = (float*)(smem_raw + WS_FLOATS * 4 + H2_ULLS * 8);  // [BROWS][TT]

    const float* x; const float* wih; const float* whh; const float* bias;
    float* hout; int coloff;
    switch (blockIdx.y) {
        case 0:  x = x0; wih = q00_wih; whh = q00_whh; bias = q00_b; hout = g_hq; coloff = 0;   break;
        case 1:  x = x1; wih = q01_wih; whh = q01_whh; bias = q01_b; hout = g_hq; coloff = 64;  break;
        case 2:  x = x2; wih = q01_wih; whh = q01_whh; bias = q01_b; hout = g_hq; coloff = 128; break;
        case 3:  x = x0; wih = i00_wih; whh = i00_whh; bias = i00_b; hout = g_hi; coloff = 0;   break;
        case 4:  x = x1; wih = i01_wih; whh = i01_whh; bias = i01_b; hout = g_hi; coloff = 64;  break;
        default: x = x2; wih = i02_wih; whh = i02_whh; bias = i02_b; hout = g_hi; coloff = 128; break;
    }

    const int tid = threadIdx.x;
    const int gi = tid & 31;
    const int ri = tid >> 5;
    const int r0 = blockIdx.x * BROWS;

    // stage whh transposed+permuted: ws[k][u*4+t] = whh[(t*64+u)*64 + k]
    // lanes take consecutive permuted columns -> smem writes conflict-free;
    // global reads scattered but L2-served (weights shared by 64 CTAs).
    for (int idx = tid; idx < 64 * 256; idx += 256) {
        int k = idx >> 8;
        int p = idx & 255;
        int tg = p & 3;
        int u  = p >> 2;
        ws[k * 256 + p] = whh[(tg * 64 + u) * 64 + k];
    }
    // x tile (coalesced)
    for (int idx = tid; idx < BROWS * TT; idx += 256)
        xs[idx] = x[r0 * TT + idx];
    // zero duplicated h state
    for (int idx = tid; idx < H2_ULLS; idx += 256)
        h2[idx] = 0ull;

    // per-thread packed gate constants (bias + wih; input dim is 1)
    ull bf2[4], wi2[4];
    #pragma unroll
    for (int jj = 0; jj < 4; ++jj) {
        int j0 = jj * 2, j1 = jj * 2 + 1;
        int g0 = (j0 & 3) * 64 + gi * 2 + (j0 >> 2);
        int g1 = (j1 & 3) * 64 + gi * 2 + (j1 >> 2);
        bf2[jj] = pack2(bias[g0], bias[g1]);
        wi2[jj] = pack2(wih[g0], wih[g1]);
    }
    float c[16];
    #pragma unroll
    for (int i = 0; i < 16; ++i) c[i] = 0.f;

    __syncthreads();

    const int gbase = gi * 8;   // permuted-column base (floats)
    for (int t = 0; t < TT; ++t) {
        ull acc2[8][4];
        #pragma unroll
        for (int r = 0; r < 8; ++r) {
            float xv = xs[(ri * 8 + r) * TT + t];
            ull xv2 = pack2(xv, xv);
            #pragma unroll
            for (int jj = 0; jj < 4; ++jj)
                acc2[r][jj] = ffma2(xv2, wi2[jj], bf2[jj]);
        }
        if (t > 0) {
            #pragma unroll 2
            for (int k = 0; k < HH; ++k) {
                const ulonglong2* wp = (const ulonglong2*)&ws[k * 256 + gbase];
                ulonglong2 wA = wp[0];   // packed gate pairs {j0,j1},{j2,j3}
                ulonglong2 wB = wp[1];   // {j4,j5},{j6,j7}
                #pragma unroll
                for (int r = 0; r < 8; ++r) {
                    ull hv2 = h2[(ri * 8 + r) * HSTR2 + k];   // {h,h}, warp-broadcast
                    acc2[r][0] = ffma2(hv2, wA.x, acc2[r][0]);
                    acc2[r][1] = ffma2(hv2, wA.y, acc2[r][1]);
                    acc2[r][2] = ffma2(hv2, wB.x, acc2[r][2]);
                    acc2[r][3] = ffma2(hv2, wB.y, acc2[r][3]);
                }
            }
        }
        // elementwise LSTM cell (c in registers)
        float hn0[8], hn1[8];
        #pragma unroll
        for (int r = 0; r < 8; ++r) {
            float iv, fv, gv, ov;
            unpack2(acc2[r][0], iv, fv);
            unpack2(acc2[r][1], gv, ov);
            float cc = sigf(fv) * c[r * 2] + sigf(iv) * tanhf_(gv);
            c[r * 2] = cc;
            hn0[r] = sigf(ov) * tanhf_(cc);
            unpack2(acc2[r][2], iv, fv);
            unpack2(acc2[r][3], gv, ov);
            cc = sigf(fv) * c[r * 2 + 1] + sigf(iv) * tanhf_(gv);
            c[r * 2 + 1] = cc;
            hn1[r] = sigf(ov) * tanhf_(cc);
        }
        __syncthreads();   // all reads of old h done
        if (t == TT - 1) {
            #pragma unroll
            for (int r = 0; r < 8; ++r) {
                int row = r0 + ri * 8 + r;
                hout[row * 192 + coloff + gi * 2 + 0] = hn0[r];
                hout[row * 192 + coloff + gi * 2 + 1] = hn1[r];
            }
        } else {
            #pragma unroll
            for (int r = 0; r < 8; ++r) {
                h2[(ri * 8 + r) * HSTR2 + gi * 2 + 0] = pack2(hn0[r], hn0[r]);
                h2[(ri * 8 + r) * HSTR2 + gi * 2 + 1] = pack2(hn1[r], hn1[r]);
            }
            __syncthreads();  // new h visible
        }
    }
}

// Head: 64 CTAs x 256 threads, 64 batch rows per CTA. w1 staged transposed in
// smem once per CTA per branch (was the L1-thrash hot spot: 79% L1, 157us).
__global__ __launch_bounds__(256) void head_kernel(
    const float* __restrict__ s2,
    const float* __restrict__ q03_w, const float* __restrict__ q03_b,
    const float* __restrict__ q1_w,  const float* __restrict__ q1_b,
    const float* __restrict__ q2_w,  const float* __restrict__ q2_b,
    const float* __restrict__ i03_w, const float* __restrict__ i03_b,
    const float* __restrict__ i1_w,  const float* __restrict__ i1_b,
    const float* __restrict__ i2_w,  const float* __restrict__ i2_b,
    float* __restrict__ out)
{
    extern __shared__ float hs[];
    float* wt  = hs;                          // [256][WT_STR]  transposed w1
    float* buf = wt + 256 * WT_STR;           // [64][BUF_STR]  concat vectors
    float* qb  = buf + 64 * BUF_STR;          // [64][QB_STR]   relu(h@w1+b1)
    float* ib  = qb + 64 * QB_STR;            // [64][8]        i vec per row

    const int tid = threadIdx.x;
    const int gi = tid & 31;
    const int ri = tid >> 5;
    const int row0 = blockIdx.x * 64;

    #pragma unroll 1
    for (int br = 0; br < 2; ++br) {
        const float* gh  = br ? g_hi  : g_hq;
        const float* w03 = br ? i03_w : q03_w;
        const float* b03 = br ? i03_b : q03_b;
        const float* w1  = br ? i1_w  : q1_w;
        const float* b1  = br ? i1_b  : q1_b;
        const float* w2  = br ? i2_w  : q2_w;
        const float* b2  = br ? i2_b  : q2_b;

        __syncthreads();   // guard smem reuse across branches

        // stage w1 transposed: wt[k][u] = w1[u*256+k]; coalesced reads,
        // smem write stride WT_STR=66 -> 2-bank stagger (near conflict-free)
        for (int idx = tid; idx < 64 * 256; idx += 256) {
            int u = idx >> 8;
            int k = idx & 255;
            wt[k * WT_STR + u] = w1[idx];
        }
        // build concat buf: [0:192) from lstm outputs, [192:256) = relu(s2@w03+b03)
        for (int idx = tid; idx < 64 * 192; idx += 256) {
            int r = idx / 192;
            int k = idx - r * 192;
            buf[r * BUF_STR + k] = gh[(row0 + r) * 192 + k];
        }
        for (int idx = tid; idx < 64 * 64; idx += 256) {
            int r = idx >> 6;
            int u = idx & 63;
            const float* s = &s2[(row0 + r) * 3];
            float a = b03[u] + s[0] * w03[u * 3] + s[1] * w03[u * 3 + 1] + s[2] * w03[u * 3 + 2];
            buf[r * BUF_STR + 192 + u] = fmaxf(a, 0.f);
        }
        __syncthreads();

        // register-tiled GEMV: thread (gi,ri) -> rows ri*8..+7, outs gi*2..+1
        float a0[8], a1[8];
        {
            float bb0 = b1[gi * 2], bb1 = b1[gi * 2 + 1];
            #pragma unroll
            for (int r = 0; r < 8; ++r) { a0[r] = bb0; a1[r] = bb1; }
        }
        #pragma unroll 4
        for (int k = 0; k < 256; ++k) {
            float2 wv = *(const float2*)&wt[k * WT_STR + gi * 2];
            #pragma unroll
            for (int r = 0; r < 8; ++r) {
                float hv = buf[(ri * 8 + r) * BUF_STR + k];
                a0[r] = fmaf(hv, wv.x, a0[r]);
                a1[r] = fmaf(hv, wv.y, a1[r]);
            }
        }
        #pragma unroll
        for (int r = 0; r < 8; ++r)
            *(float2*)&qb[(ri * 8 + r) * QB_STR + gi * 2] =
                make_float2(fmaxf(a0[r], 0.f), fmaxf(a1[r], 0.f));
        __syncthreads();

        // final 6-wide projection
        for (int it = tid; it < 64 * AA; it += 256) {
            int r = it / AA;
            int a = it - r * AA;
            float acc = b2[a];
            #pragma unroll 8
            for (int k = 0; k < 64; ++k)
                acc = fmaf(w2[a * 64 + k], qb[r * QB_STR + k], acc);
            if (br == 0) {
                out[(row0 + r) * AA + a] = acc;        // q (no relu)
            } else {
                ib[r * 8 + a] = fmaxf(acc, 0.f);       // i vec
            }
        }
        if (br == 1) {
            __syncthreads();
            if (tid < 64) {
                int r = tid;
                float m = ib[r * 8];
                #pragma unroll
                for (int j = 1; j < AA; ++j) m = fmaxf(m, ib[r * 8 + j]);
                float s = 0.f;
                #pragma unroll
                for (int j = 0; j < AA; ++j) s += __expf(ib[r * 8 + j] - m);
                float lse = m + __logf(s);
                #pragma unroll
                for (int j = 0; j < AA; ++j) {
                    float iv = ib[r * 8 + j];
                    out[BB * AA + (row0 + r) * AA + j]     = iv - lse;
                    out[2 * BB * AA + (row0 + r) * AA + j] = iv;
                }
            }
        }
    }
}

extern "C" void kernel_launch(void* const* d_in, const int* in_sizes, int n_in,
                              void* d_out, int out_size)
{
    const float* x0 = (const float*)d_in[0];
    const float* x1 = (const float*)d_in[1];
    const float* x2 = (const float*)d_in[2];
    const float* s2 = (const float*)d_in[3];
    const float* q00_wih = (const float*)d_in[4];
    const float* q00_whh = (const float*)d_in[5];
    const float* q00_b   = (const float*)d_in[6];
    const float* q01_wih = (const float*)d_in[7];
    const float* q01_whh = (const float*)d_in[8];
    const float* q01_b   = (const float*)d_in[9];
    const float* i00_wih = (const float*)d_in[10];
    const float* i00_whh = (const float*)d_in[11];
    const float* i00_b   = (const float*)d_in[12];
    const float* i01_wih = (const float*)d_in[13];
    const float* i01_whh = (const float*)d_in[14];
    const float* i01_b   = (const float*)d_in[15];
    const float* i02_wih = (const float*)d_in[16];
    const float* i02_whh = (const float*)d_in[17];
    const float* i02_b   = (const float*)d_in[18];
    const float* q03_w = (const float*)d_in[19];
    const float* q03_b = (const float*)d_in[20];
    const float* q1_w  = (const float*)d_in[21];
    const float* q1_b  = (const float*)d_in[22];
    const float* q2_w  = (const float*)d_in[23];
    const float* q2_b  = (const float*)d_in[24];
    const float* i03_w = (const float*)d_in[25];
    const float* i03_b = (const float*)d_in[26];
    const float* i1_w  = (const float*)d_in[27];
    const float* i1_b  = (const float*)d_in[28];
    const float* i2_w  = (const float*)d_in[29];
    const float* i2_b  = (const float*)d_in[30];
    float* out = (float*)d_out;

    cudaFuncSetAttribute(lstm_kernel, cudaFuncAttributeMaxDynamicSharedMemorySize, LSTM_SMEM_BYTES);
    cudaFuncSetAttribute(head_kernel, cudaFuncAttributeMaxDynamicSharedMemorySize, HEAD_SMEM_BYTES);

    dim3 grid(BB / BROWS, 6);   // 64 batch tiles x 6 LSTM runs
    lstm_kernel<<<grid, 256, LSTM_SMEM_BYTES>>>(
        x0, x1, x2,
        q00_wih, q00_whh, q00_b,
        q01_wih, q01_whh, q01_b,
        i00_wih, i00_whh, i00_b,
        i01_wih, i01_whh, i01_b,
        i02_wih, i02_whh, i02_b);

    head_kernel<<<BB / 64, 256, HEAD_SMEM_BYTES>>>(
        s2,
        q03_w, q03_b, q1_w, q1_b, q2_w, q2_b,
        i03_w, i03_b, i1_w, i1_b, i2_w, i2_b,
        out);
}

// round 6
// speedup vs baseline: 2.7840x; 2.7836x over previous
#include <cuda_runtime.h>
#include <cuda_bf16.h>

// Problem constants
#define HH    64
#define TT    32
#define BB    4096
#define AA    6
#define MROWS 32        // batch rows per lstm CTA

// lstm smem layout (bytes). Rows padded to 144B (72 bf16) for conflict-free ldmatrix.
#define OFF_WSHI 0                   // Ws_hi [256][72] bf16 : weights hi, [p][k]
#define OFF_WSLO 36864               // Ws_lo
#define OFF_HSHI 73728               // hs_hi [32][72] bf16  : h hi, [row][unit]
#define OFF_HSLO 78336               // hs_lo
#define OFF_WBS  82944               // float2[256] permuted {wih, b}
#define OFF_XS   84992               // float [32][33]
#define LSTM_SMEM_BYTES (OFF_XS + 32 * 33 * 4)   // 89216

// head kernel smem (floats)
#define WT_STR 66
#define BUF_STR 260
#define QB_STR 66
#define HEAD_SMEM_FLOATS (256 * WT_STR + 64 * BUF_STR + 64 * QB_STR + 64 * 8)
#define HEAD_SMEM_BYTES (HEAD_SMEM_FLOATS * 4)

// scratch: final hidden states, [B][192] (3 LSTM outputs per branch)
__device__ float g_hq[BB * 192];
__device__ float g_hi[BB * 192];

__device__ __forceinline__ float sigf(float x) {
    return __fdividef(1.f, 1.f + __expf(-x));
}
__device__ __forceinline__ float tanhf_(float x) {
    return 1.f - __fdividef(2.f, __expf(2.f * x) + 1.f);
}

__device__ __forceinline__ unsigned smem_u32(const void* p) {
    unsigned a;
    asm("{ .reg .u64 t; cvta.to.shared.u64 t, %1; cvt.u32.u64 %0, t; }" : "=r"(a) : "l"(p));
    return a;
}
__device__ __forceinline__ void ldsm_x4(unsigned addr, unsigned& r0, unsigned& r1,
                                        unsigned& r2, unsigned& r3) {
    asm volatile("ldmatrix.sync.aligned.m8n8.x4.shared.b16 {%0,%1,%2,%3}, [%4];"
                 : "=r"(r0), "=r"(r1), "=r"(r2), "=r"(r3) : "r"(addr));
}
__device__ __forceinline__ void mma16816(float& d0, float& d1, float& d2, float& d3,
                                         unsigned a0, unsigned a1, unsigned a2, unsigned a3,
                                         unsigned b0, unsigned b1) {
    asm volatile(
        "mma.sync.aligned.m16n8k16.row.col.f32.bf16.bf16.f32 "
        "{%0,%1,%2,%3}, {%4,%5,%6,%7}, {%8,%9}, {%0,%1,%2,%3};"
        : "+f"(d0), "+f"(d1), "+f"(d2), "+f"(d3)
        : "r"(a0), "r"(a1), "r"(a2), "r"(a3), "r"(b0), "r"(b1));
}

// One CTA: 32 batch rows x one LSTM run. Recurrent matmul on HMMA (mma.sync)
// with bf16 hi/lo 3-term split. 8 warps: rg = wid&1 (16-row group),
// gq = wid>>1 (64-gate quarter). Gate columns permuted
// p = (u&3)*2 + (tg&1) + 8*(tg>>1) + 16*(u>>2) so each thread's accumulator
// fragments hold all four gates of its units -> c state in registers.
__global__ __launch_bounds__(256, 2) void lstm_mma_kernel(
    const float* __restrict__ x0, const float* __restrict__ x1, const float* __restrict__ x2,
    const float* __restrict__ q00_wih, const float* __restrict__ q00_whh, const float* __restrict__ q00_b,
    const float* __restrict__ q01_wih, const float* __restrict__ q01_whh, const float* __restrict__ q01_b,
    const float* __restrict__ i00_wih, const float* __restrict__ i00_whh, const float* __restrict__ i00_b,
    const float* __restrict__ i01_wih, const float* __restrict__ i01_whh, const float* __restrict__ i01_b,
    const float* __restrict__ i02_wih, const float* __restrict__ i02_whh, const float* __restrict__ i02_b)
{
    extern __shared__ char smem[];
    const unsigned sb = smem_u32(smem);

    const float* x; const float* wih; const float* whh; const float* bias;
    float* hout; int coloff;
    switch (blockIdx.y) {
        case 0:  x = x0; wih = q00_wih; whh = q00_whh; bias = q00_b; hout = g_hq; coloff = 0;   break;
        case 1:  x = x1; wih = q01_wih; whh = q01_whh; bias = q01_b; hout = g_hq; coloff = 64;  break;
        case 2:  x = x2; wih = q01_wih; whh = q01_whh; bias = q01_b; hout = g_hq; coloff = 128; break;
        case 3:  x = x0; wih = i00_wih; whh = i00_whh; bias = i00_b; hout = g_hi; coloff = 0;   break;
        case 4:  x = x1; wih = i01_wih; whh = i01_whh; bias = i01_b; hout = g_hi; coloff = 64;  break;
        default: x = x2; wih = i02_wih; whh = i02_whh; bias = i02_b; hout = g_hi; coloff = 128; break;
    }

    const int tid  = threadIdx.x;
    const int wid  = tid >> 5;
    const int lane = tid & 31;
    const int rg   = wid & 1;        // 16-row group
    const int gq   = wid >> 1;       // 64-gate quarter (0..3)
    const int g    = lane >> 2;
    const int tl   = lane & 3;
    const int r0g  = blockIdx.x * MROWS;

    // ---- stage whh split+permuted: Ws[p][k] with p = perm(u, tg) ----
    __nv_bfloat16* wshi = (__nv_bfloat16*)(smem + OFF_WSHI);
    __nv_bfloat16* wslo = (__nv_bfloat16*)(smem + OFF_WSLO);
    for (int idx = tid; idx < 256 * 64; idx += 256) {
        int go = idx >> 6, k = idx & 63;
        int tg = go >> 6, u = go & 63;
        int p  = (u & 3) * 2 + (tg & 1) + 8 * (tg >> 1) + 16 * (u >> 2);
        float w = whh[idx];
        __nv_bfloat16 hi = __float2bfloat16(w);
        __nv_bfloat16 lo = __float2bfloat16(w - __bfloat162float(hi));
        wshi[p * 72 + k] = hi;
        wslo[p * 72 + k] = lo;
    }
    // permuted {wih, b}
    {
        int go = tid;
        int tg = go >> 6, u = go & 63;
        int p  = (u & 3) * 2 + (tg & 1) + 8 * (tg >> 1) + 16 * (u >> 2);
        ((float2*)(smem + OFF_WBS))[p] = make_float2(wih[go], bias[go]);
    }
    // zero h (hi+lo incl. padding)
    for (int idx = tid; idx < 1152; idx += 256) {
        ((unsigned*)(smem + OFF_HSHI))[idx] = 0u;
        ((unsigned*)(smem + OFF_HSLO))[idx] = 0u;
    }
    // x tile [32][33]
    float* xs = (float*)(smem + OFF_XS);
    for (int idx = tid; idx < MROWS * TT; idx += 256) {
        int r = idx >> 5, tt = idx & 31;
        xs[r * 33 + tt] = x[(size_t)(r0g + r) * TT + tt];
    }
    __syncthreads();

    // per-lane ldmatrix addresses
    const int rowA  = rg * 16 + (lane & 7) + 8 * ((lane >> 3) & 1);
    const unsigned aoff = (unsigned)(rowA * 144 + (lane >> 4) * 16);
    const int rowBb = gq * 64 + (lane & 7) + 8 * (lane >> 4);
    const unsigned boff = (unsigned)(rowBb * 144 + ((lane >> 3) & 1) * 16);

    const int r0 = rg * 16 + g;       // this thread's rows
    const int r1 = r0 + 8;

    float cst[8];
    #pragma unroll
    for (int i = 0; i < 8; ++i) cst[i] = 0.f;

    __nv_bfloat16* hshi = (__nv_bfloat16*)(smem + OFF_HSHI);
    __nv_bfloat16* hslo = (__nv_bfloat16*)(smem + OFF_HSLO);
    const float4* wbs4 = (const float4*)(smem + OFF_WBS);

    #pragma unroll 1
    for (int t = 0; t < TT; ++t) {
        float acc[32];
        #pragma unroll
        for (int i = 0; i < 32; ++i) acc[i] = 0.f;

        #pragma unroll
        for (int kc = 0; kc < 4; ++kc) {
            unsigned ah0, ah1, ah2, ah3, al0, al1, al2, al3;
            ldsm_x4(sb + OFF_HSHI + aoff + kc * 32, ah0, ah1, ah2, ah3);
            ldsm_x4(sb + OFF_HSLO + aoff + kc * 32, al0, al1, al2, al3);
            #pragma unroll
            for (int np = 0; np < 4; ++np) {
                unsigned bh0, bh1, bh2, bh3, bl0, bl1, bl2, bl3;
                unsigned bb = boff + (unsigned)(np * 16 * 144 + kc * 32);
                ldsm_x4(sb + OFF_WSHI + bb, bh0, bh1, bh2, bh3);
                ldsm_x4(sb + OFF_WSLO + bb, bl0, bl1, bl2, bl3);
                float* e = acc + np * 8;        // ntiles 2np, 2np+1
                mma16816(e[0], e[1], e[2], e[3], ah0, ah1, ah2, ah3, bh0, bh1);
                mma16816(e[4], e[5], e[6], e[7], ah0, ah1, ah2, ah3, bh2, bh3);
                mma16816(e[0], e[1], e[2], e[3], al0, al1, al2, al3, bh0, bh1);
                mma16816(e[4], e[5], e[6], e[7], al0, al1, al2, al3, bh2, bh3);
                mma16816(e[0], e[1], e[2], e[3], ah0, ah1, ah2, ah3, bl0, bl1);
                mma16816(e[4], e[5], e[6], e[7], ah0, ah1, ah2, ah3, bl2, bl3);
            }
        }
        __syncthreads();   // all warps' ldmatrix reads of hs complete

        float xv0 = xs[r0 * 33 + t];
        float xv1 = xs[r1 * 33 + t];
        #pragma unroll
        for (int q = 0; q < 4; ++q) {
            int pq = 16 * (gq * 4 + q) + 2 * tl;
            float4 wif = wbs4[pq >> 1];          // (wih_i, b_i, wih_f, b_f)
            float4 wgo = wbs4[(pq >> 1) + 4];    // (wih_g, b_g, wih_o, b_o)
            int u = 16 * gq + 4 * q + tl;        // real unit index
            #pragma unroll
            for (int rowj = 0; rowj < 2; ++rowj) {
                float xv = rowj ? xv1 : xv0;
                float iv = acc[(2 * q) * 4 + rowj * 2 + 0] + fmaf(wif.x, xv, wif.y);
                float fv = acc[(2 * q) * 4 + rowj * 2 + 1] + fmaf(wif.z, xv, wif.w);
                float gv = acc[(2 * q + 1) * 4 + rowj * 2 + 0] + fmaf(wgo.x, xv, wgo.y);
                float ov = acc[(2 * q + 1) * 4 + rowj * 2 + 1] + fmaf(wgo.z, xv, wgo.w);
                float cc = sigf(fv) * cst[q * 2 + rowj] + sigf(iv) * tanhf_(gv);
                cst[q * 2 + rowj] = cc;
                float h = sigf(ov) * tanhf_(cc);
                int row = rowj ? r1 : r0;
                if (t < TT - 1) {
                    __nv_bfloat16 hi = __float2bfloat16(h);
                    hshi[row * 72 + u] = hi;
                    hslo[row * 72 + u] = __float2bfloat16(h - __bfloat162float(hi));
                } else {
                    hout[(size_t)(r0g + row) * 192 + coloff + u] = h;
                }
            }
        }
        if (t < TT - 1) __syncthreads();   // new h visible before next step's reads
    }
}

// Head: grid (64, 2): 64 row-tiles x 2 branches; w1 staged transposed in smem.
__global__ __launch_bounds__(256) void head_kernel(
    const float* __restrict__ s2,
    const float* __restrict__ q03_w, const float* __restrict__ q03_b,
    const float* __restrict__ q1_w,  const float* __restrict__ q1_b,
    const float* __restrict__ q2_w,  const float* __restrict__ q2_b,
    const float* __restrict__ i03_w, const float* __restrict__ i03_b,
    const float* __restrict__ i1_w,  const float* __restrict__ i1_b,
    const float* __restrict__ i2_w,  const float* __restrict__ i2_b,
    float* __restrict__ out)
{
    extern __shared__ float hs[];
    float* wt  = hs;                          // [256][WT_STR]
    float* buf = wt + 256 * WT_STR;           // [64][BUF_STR]
    float* qb  = buf + 64 * BUF_STR;          // [64][QB_STR]
    float* ib  = qb + 64 * QB_STR;            // [64][8]

    const int tid  = threadIdx.x;
    const int gi   = tid & 31;
    const int ri   = tid >> 5;
    const int row0 = blockIdx.x * 64;
    const int br   = blockIdx.y;

    const float* gh  = br ? g_hi  : g_hq;
    const float* w03 = br ? i03_w : q03_w;
    const float* b03 = br ? i03_b : q03_b;
    const float* w1  = br ? i1_w  : q1_w;
    const float* b1  = br ? i1_b  : q1_b;
    const float* w2  = br ? i2_w  : q2_w;
    const float* b2  = br ? i2_b  : q2_b;

    for (int idx = tid; idx < 64 * 256; idx += 256) {
        int u = idx >> 8, k = idx & 255;
        wt[k * WT_STR + u] = w1[idx];
    }
    for (int idx = tid; idx < 64 * 192; idx += 256) {
        int r = idx / 192, k = idx - r * 192;
        buf[r * BUF_STR + k] = gh[(row0 + r) * 192 + k];
    }
    for (int idx = tid; idx < 64 * 64; idx += 256) {
        int r = idx >> 6, u = idx & 63;
        const float* s = &s2[(row0 + r) * 3];
        float a = b03[u] + s[0] * w03[u * 3] + s[1] * w03[u * 3 + 1] + s[2] * w03[u * 3 + 2];
        buf[r * BUF_STR + 192 + u] = fmaxf(a, 0.f);
    }
    __syncthreads();

    float a0[8], a1[8];
    {
        float bb0 = b1[gi * 2], bb1 = b1[gi * 2 + 1];
        #pragma unroll
        for (int r = 0; r < 8; ++r) { a0[r] = bb0; a1[r] = bb1; }
    }
    #pragma unroll 4
    for (int k = 0; k < 256; ++k) {
        float2 wv = *(const float2*)&wt[k * WT_STR + gi * 2];
        #pragma unroll
        for (int r = 0; r < 8; ++r) {
            float hv = buf[(ri * 8 + r) * BUF_STR + k];
            a0[r] = fmaf(hv, wv.x, a0[r]);
            a1[r] = fmaf(hv, wv.y, a1[r]);
        }
    }
    #pragma unroll
    for (int r = 0; r < 8; ++r)
        *(float2*)&qb[(ri * 8 + r) * QB_STR + gi * 2] =
            make_float2(fmaxf(a0[r], 0.f), fmaxf(a1[r], 0.f));
    __syncthreads();

    for (int it = tid; it < 64 * AA; it += 256) {
        int r = it / AA;
        int a = it - r * AA;
        float acc = b2[a];
        #pragma unroll 8
        for (int k = 0; k < 64; ++k)
            acc = fmaf(w2[a * 64 + k], qb[r * QB_STR + k], acc);
        if (br == 0) out[(row0 + r) * AA + a] = acc;        // q (no relu)
        else         ib[r * 8 + a] = fmaxf(acc, 0.f);       // i vec
    }
    if (br == 1) {
        __syncthreads();
        if (tid < 64) {
            int r = tid;
            float m = ib[r * 8];
            #pragma unroll
            for (int j = 1; j < AA; ++j) m = fmaxf(m, ib[r * 8 + j]);
            float s = 0.f;
            #pragma unroll
            for (int j = 0; j < AA; ++j) s += __expf(ib[r * 8 + j] - m);
            float lse = m + __logf(s);
            #pragma unroll
            for (int j = 0; j < AA; ++j) {
                float iv = ib[r * 8 + j];
                out[BB * AA + (row0 + r) * AA + j]     = iv - lse;
                out[2 * BB * AA + (row0 + r) * AA + j] = iv;
            }
        }
    }
}

extern "C" void kernel_launch(void* const* d_in, const int* in_sizes, int n_in,
                              void* d_out, int out_size)
{
    const float* x0 = (const float*)d_in[0];
    const float* x1 = (const float*)d_in[1];
    const float* x2 = (const float*)d_in[2];
    const float* s2 = (const float*)d_in[3];
    const float* q00_wih = (const float*)d_in[4];
    const float* q00_whh = (const float*)d_in[5];
    const float* q00_b   = (const float*)d_in[6];
    const float* q01_wih = (const float*)d_in[7];
    const float* q01_whh = (const float*)d_in[8];
    const float* q01_b   = (const float*)d_in[9];
    const float* i00_wih = (const float*)d_in[10];
    const float* i00_whh = (const float*)d_in[11];
    const float* i00_b   = (const float*)d_in[12];
    const float* i01_wih = (const float*)d_in[13];
    const float* i01_whh = (const float*)d_in[14];
    const float* i01_b   = (const float*)d_in[15];
    const float* i02_wih = (const float*)d_in[16];
    const float* i02_whh = (const float*)d_in[17];
    const float* i02_b   = (const float*)d_in[18];
    const float* q03_w = (const float*)d_in[19];
    const float* q03_b = (const float*)d_in[20];
    const float* q1_w  = (const float*)d_in[21];
    const float* q1_b  = (const float*)d_in[22];
    const float* q2_w  = (const float*)d_in[23];
    const float* q2_b  = (const float*)d_in[24];
    const float* i03_w = (const float*)d_in[25];
    const float* i03_b = (const float*)d_in[26];
    const float* i1_w  = (const float*)d_in[27];
    const float* i1_b  = (const float*)d_in[28];
    const float* i2_w  = (const float*)d_in[29];
    const float* i2_b  = (const float*)d_in[30];
    float* out = (float*)d_out;

    cudaFuncSetAttribute(lstm_mma_kernel, cudaFuncAttributeMaxDynamicSharedMemorySize, LSTM_SMEM_BYTES);
    cudaFuncSetAttribute(head_kernel, cudaFuncAttributeMaxDynamicSharedMemorySize, HEAD_SMEM_BYTES);

    dim3 grid(BB / MROWS, 6);   // 128 batch tiles x 6 LSTM runs = 768 CTAs, 2/SM
    lstm_mma_kernel<<<grid, 256, LSTM_SMEM_BYTES>>>(
        x0, x1, x2,
        q00_wih, q00_whh, q00_b,
        q01_wih, q01_whh, q01_b,
        i00_wih, i00_whh, i00_b,
        i01_wih, i01_whh, i01_b,
        i02_wih, i02_whh, i02_b);

    head_kernel<<<dim3(64, 2), 256, HEAD_SMEM_BYTES>>>(
        s2,
        q03_w, q03_b, q1_w, q1_b, q2_w, q2_b,
        i03_w, i03_b, i1_w, i1_b, i2_w, i2_b,
        out);
}

// round 7
// speedup vs baseline: 4.5039x; 1.6178x over previous
#include <cuda_runtime.h>
#include <cuda_fp16.h>

// Problem constants
#define HH    64
#define TT    32
#define BB    4096
#define AA    6
#define MROWS 32        // batch rows per lstm CTA

// lstm smem layout (bytes). Rows padded to 144B (72 halves) for conflict-free ldmatrix.
#define OFF_WS  0                    // Ws [256][72] half : weights fp16, [p][k]
#define OFF_HS  36864                // hs [32][72] half  : h fp16, [row][unit]
#define OFF_WBS 41472                // float2[256] permuted {wih, b}
#define OFF_XS  43520                // float [32][33]
#define LSTM_SMEM_BYTES (OFF_XS + 32 * 33 * 4)   // 47744

// head kernel smem (floats)
#define WT_STR 66
#define BUF_STR 260
#define QB_STR 66
#define HEAD_SMEM_FLOATS (256 * WT_STR + 64 * BUF_STR + 64 * QB_STR + 64 * 8)
#define HEAD_SMEM_BYTES (HEAD_SMEM_FLOATS * 4)

// scratch: final hidden states, [B][192] (3 LSTM outputs per branch)
__device__ float g_hq[BB * 192];
__device__ float g_hi[BB * 192];

__device__ __forceinline__ float tanh_ap(float x) {
    float y;
    asm("tanh.approx.f32 %0, %1;" : "=f"(y) : "f"(x));
    return y;
}
__device__ __forceinline__ float sig_ap(float x) {
    return fmaf(0.5f, tanh_ap(0.5f * x), 0.5f);
}

__device__ __forceinline__ unsigned smem_u32(const void* p) {
    unsigned a;
    asm("{ .reg .u64 t; cvta.to.shared.u64 t, %1; cvt.u32.u64 %0, t; }" : "=r"(a) : "l"(p));
    return a;
}
__device__ __forceinline__ void ldsm_x4(unsigned addr, unsigned& r0, unsigned& r1,
                                        unsigned& r2, unsigned& r3) {
    asm volatile("ldmatrix.sync.aligned.m8n8.x4.shared.b16 {%0,%1,%2,%3}, [%4];"
                 : "=r"(r0), "=r"(r1), "=r"(r2), "=r"(r3) : "r"(addr));
}
__device__ __forceinline__ void mma16816(float& d0, float& d1, float& d2, float& d3,
                                         unsigned a0, unsigned a1, unsigned a2, unsigned a3,
                                         unsigned b0, unsigned b1) {
    asm volatile(
        "mma.sync.aligned.m16n8k16.row.col.f32.f16.f16.f32 "
        "{%0,%1,%2,%3}, {%4,%5,%6,%7}, {%8,%9}, {%0,%1,%2,%3};"
        : "+f"(d0), "+f"(d1), "+f"(d2), "+f"(d3)
        : "r"(a0), "r"(a1), "r"(a2), "r"(a3), "r"(b0), "r"(b1));
}

// One CTA: 32 batch rows x one LSTM run. Recurrent matmul on HMMA (mma.sync)
// single-term fp16 (error budget: per-product ~2^-11, ~19x attenuation to
// output -> ~2.5e-5 final). 8 warps: rg = wid&1 (16-row group), gq = wid>>1
// (64-gate quarter). Gate columns permuted
// p = (u&3)*2 + (tg&1) + 8*(tg>>1) + 16*(u>>2) so each thread's accumulator
// fragments hold all four gates of its units -> c state in registers.
__global__ __launch_bounds__(256, 2) void lstm_mma_kernel(
    const float* __restrict__ x0, const float* __restrict__ x1, const float* __restrict__ x2,
    const float* __restrict__ q00_wih, const float* __restrict__ q00_whh, const float* __restrict__ q00_b,
    const float* __restrict__ q01_wih, const float* __restrict__ q01_whh, const float* __restrict__ q01_b,
    const float* __restrict__ i00_wih, const float* __restrict__ i00_whh, const float* __restrict__ i00_b,
    const float* __restrict__ i01_wih, const float* __restrict__ i01_whh, const float* __restrict__ i01_b,
    const float* __restrict__ i02_wih, const float* __restrict__ i02_whh, const float* __restrict__ i02_b)
{
    extern __shared__ char smem[];
    const unsigned sb = smem_u32(smem);

    const float* x; const float* wih; const float* whh; const float* bias;
    float* hout; int coloff;
    switch (blockIdx.y) {
        case 0:  x = x0; wih = q00_wih; whh = q00_whh; bias = q00_b; hout = g_hq; coloff = 0;   break;
        case 1:  x = x1; wih = q01_wih; whh = q01_whh; bias = q01_b; hout = g_hq; coloff = 64;  break;
        case 2:  x = x2; wih = q01_wih; whh = q01_whh; bias = q01_b; hout = g_hq; coloff = 128; break;
        case 3:  x = x0; wih = i00_wih; whh = i00_whh; bias = i00_b; hout = g_hi; coloff = 0;   break;
        case 4:  x = x1; wih = i01_wih; whh = i01_whh; bias = i01_b; hout = g_hi; coloff = 64;  break;
        default: x = x2; wih = i02_wih; whh = i02_whh; bias = i02_b; hout = g_hi; coloff = 128; break;
    }

    const int tid  = threadIdx.x;
    const int wid  = tid >> 5;
    const int lane = tid & 31;
    const int rg   = wid & 1;        // 16-row group
    const int gq   = wid >> 1;       // 64-gate quarter (0..3)
    const int g    = lane >> 2;
    const int tl   = lane & 3;
    const int r0g  = blockIdx.x * MROWS;

    // ---- stage whh fp16, permuted: Ws[p][k] with p = perm(u, tg) ----
    __half* ws = (__half*)(smem + OFF_WS);
    for (int idx = tid; idx < 256 * 64; idx += 256) {
        int go = idx >> 6, k = idx & 63;
        int tg = go >> 6, u = go & 63;
        int p  = (u & 3) * 2 + (tg & 1) + 8 * (tg >> 1) + 16 * (u >> 2);
        ws[p * 72 + k] = __float2half(whh[idx]);
    }
    // permuted {wih, b}
    {
        int go = tid;
        int tg = go >> 6, u = go & 63;
        int p  = (u & 3) * 2 + (tg & 1) + 8 * (tg >> 1) + 16 * (u >> 2);
        ((float2*)(smem + OFF_WBS))[p] = make_float2(wih[go], bias[go]);
    }
    // zero h (incl. padding): 32*72 halves = 1152 u32
    for (int idx = tid; idx < 1152; idx += 256)
        ((unsigned*)(smem + OFF_HS))[idx] = 0u;
    // x tile [32][33]
    float* xs = (float*)(smem + OFF_XS);
    for (int idx = tid; idx < MROWS * TT; idx += 256) {
        int r = idx >> 5, tt = idx & 31;
        xs[r * 33 + tt] = x[(size_t)(r0g + r) * TT + tt];
    }
    __syncthreads();

    // per-lane ldmatrix addresses
    const int rowA  = rg * 16 + (lane & 7) + 8 * ((lane >> 3) & 1);
    const unsigned aoff = (unsigned)(rowA * 144 + (lane >> 4) * 16);
    const int rowBb = gq * 64 + (lane & 7) + 8 * (lane >> 4);
    const unsigned boff = (unsigned)(rowBb * 144 + ((lane >> 3) & 1) * 16);

    const int r0 = rg * 16 + g;       // this thread's rows
    const int r1 = r0 + 8;

    float cst[8];
    #pragma unroll
    for (int i = 0; i < 8; ++i) cst[i] = 0.f;

    __half* hs_ = (__half*)(smem + OFF_HS);
    const float4* wbs4 = (const float4*)(smem + OFF_WBS);

    #pragma unroll 1
    for (int t = 0; t < TT; ++t) {
        float acc[32];
        #pragma unroll
        for (int i = 0; i < 32; ++i) acc[i] = 0.f;

        if (t > 0) {
            #pragma unroll
            for (int kc = 0; kc < 4; ++kc) {
                unsigned ah0, ah1, ah2, ah3;
                ldsm_x4(sb + OFF_HS + aoff + kc * 32, ah0, ah1, ah2, ah3);
                #pragma unroll
                for (int np = 0; np < 4; ++np) {
                    unsigned bh0, bh1, bh2, bh3;
                    unsigned bb = boff + (unsigned)(np * 16 * 144 + kc * 32);
                    ldsm_x4(sb + OFF_WS + bb, bh0, bh1, bh2, bh3);
                    float* e = acc + np * 8;        // ntiles 2np, 2np+1
                    mma16816(e[0], e[1], e[2], e[3], ah0, ah1, ah2, ah3, bh0, bh1);
                    mma16816(e[4], e[5], e[6], e[7], ah0, ah1, ah2, ah3, bh2, bh3);
                }
            }
            __syncthreads();   // all warps' ldmatrix reads of hs complete
        }

        float xv0 = xs[r0 * 33 + t];
        float xv1 = xs[r1 * 33 + t];
        #pragma unroll
        for (int q = 0; q < 4; ++q) {
            int pq = 16 * (gq * 4 + q) + 2 * tl;
            float4 wif = wbs4[pq >> 1];          // (wih_i, b_i, wih_f, b_f)
            float4 wgo = wbs4[(pq >> 1) + 4];    // (wih_g, b_g, wih_o, b_o)
            int u = 16 * gq + 4 * q + tl;        // real unit index
            #pragma unroll
            for (int rowj = 0; rowj < 2; ++rowj) {
                float xv = rowj ? xv1 : xv0;
                float iv = acc[(2 * q) * 4 + rowj * 2 + 0] + fmaf(wif.x, xv, wif.y);
                float fv = acc[(2 * q) * 4 + rowj * 2 + 1] + fmaf(wif.z, xv, wif.w);
                float gv = acc[(2 * q + 1) * 4 + rowj * 2 + 0] + fmaf(wgo.x, xv, wgo.y);
                float ov = acc[(2 * q + 1) * 4 + rowj * 2 + 1] + fmaf(wgo.z, xv, wgo.w);
                float cc = sig_ap(fv) * cst[q * 2 + rowj] + sig_ap(iv) * tanh_ap(gv);
                cst[q * 2 + rowj] = cc;
                float h = sig_ap(ov) * tanh_ap(cc);
                int row = rowj ? r1 : r0;
                if (t < TT - 1) {
                    hs_[row * 72 + u] = __float2half(h);
                } else {
                    hout[(size_t)(r0g + row) * 192 + coloff + u] = h;
                }
            }
        }
        if (t < TT - 1) __syncthreads();   // new h visible before next step's reads
    }
}

// Head: grid (64, 2): 64 row-tiles x 2 branches; w1 staged transposed in smem.
__global__ __launch_bounds__(256) void head_kernel(
    const float* __restrict__ s2,
    const float* __restrict__ q03_w, const float* __restrict__ q03_b,
    const float* __restrict__ q1_w,  const float* __restrict__ q1_b,
    const float* __restrict__ q2_w,  const float* __restrict__ q2_b,
    const float* __restrict__ i03_w, const float* __restrict__ i03_b,
    const float* __restrict__ i1_w,  const float* __restrict__ i1_b,
    const float* __restrict__ i2_w,  const float* __restrict__ i2_b,
    float* __restrict__ out)
{
    extern __shared__ float hs[];
    float* wt  = hs;                          // [256][WT_STR]
    float* buf = wt + 256 * WT_STR;           // [64][BUF_STR]
    float* qb  = buf + 64 * BUF_STR;          // [64][QB_STR]
    float* ib  = qb + 64 * QB_STR;            // [64][8]

    const int tid  = threadIdx.x;
    const int gi   = tid & 31;
    const int ri   = tid >> 5;
    const int row0 = blockIdx.x * 64;
    const int br   = blockIdx.y;

    const float* gh  = br ? g_hi  : g_hq;
    const float* w03 = br ? i03_w : q03_w;
    const float* b03 = br ? i03_b : q03_b;
    const float* w1  = br ? i1_w  : q1_w;
    const float* b1  = br ? i1_b  : q1_b;
    const float* w2  = br ? i2_w  : q2_w;
    const float* b2  = br ? i2_b  : q2_b;

    for (int idx = tid; idx < 64 * 256; idx += 256) {
        int u = idx >> 8, k = idx & 255;
        wt[k * WT_STR + u] = w1[idx];
    }
    for (int idx = tid; idx < 64 * 192; idx += 256) {
        int r = idx / 192, k = idx - r * 192;
        buf[r * BUF_STR + k] = gh[(row0 + r) * 192 + k];
    }
    for (int idx = tid; idx < 64 * 64; idx += 256) {
        int r = idx >> 6, u = idx & 63;
        const float* s = &s2[(row0 + r) * 3];
        float a = b03[u] + s[0] * w03[u * 3] + s[1] * w03[u * 3 + 1] + s[2] * w03[u * 3 + 2];
        buf[r * BUF_STR + 192 + u] = fmaxf(a, 0.f);
    }
    __syncthreads();

    float a0[8], a1[8];
    {
        float bb0 = b1[gi * 2], bb1 = b1[gi * 2 + 1];
        #pragma unroll
        for (int r = 0; r < 8; ++r) { a0[r] = bb0; a1[r] = bb1; }
    }
    #pragma unroll 4
    for (int k = 0; k < 256; ++k) {
        float2 wv = *(const float2*)&wt[k * WT_STR + gi * 2];
        #pragma unroll
        for (int r = 0; r < 8; ++r) {
            float hv = buf[(ri * 8 + r) * BUF_STR + k];
            a0[r] = fmaf(hv, wv.x, a0[r]);
            a1[r] = fmaf(hv, wv.y, a1[r]);
        }
    }
    #pragma unroll
    for (int r = 0; r < 8; ++r)
        *(float2*)&qb[(ri * 8 + r) * QB_STR + gi * 2] =
            make_float2(fmaxf(a0[r], 0.f), fmaxf(a1[r], 0.f));
    __syncthreads();

    for (int it = tid; it < 64 * AA; it += 256) {
        int r = it / AA;
        int a = it - r * AA;
        float acc = b2[a];
        #pragma unroll 8
        for (int k = 0; k < 64; ++k)
            acc = fmaf(w2[a * 64 + k], qb[r * QB_STR + k], acc);
        if (br == 0) out[(row0 + r) * AA + a] = acc;        // q (no relu)
        else         ib[r * 8 + a] = fmaxf(acc, 0.f);       // i vec
    }
    if (br == 1) {
        __syncthreads();
        if (tid < 64) {
            int r = tid;
            float m = ib[r * 8];
            #pragma unroll
            for (int j = 1; j < AA; ++j) m = fmaxf(m, ib[r * 8 + j]);
            float s = 0.f;
            #pragma unroll
            for (int j = 0; j < AA; ++j) s += __expf(ib[r * 8 + j] - m);
            float lse = m + __logf(s);
            #pragma unroll
            for (int j = 0; j < AA; ++j) {
                float iv = ib[r * 8 + j];
                out[BB * AA + (row0 + r) * AA + j]     = iv - lse;
                out[2 * BB * AA + (row0 + r) * AA + j] = iv;
            }
        }
    }
}

extern "C" void kernel_launch(void* const* d_in, const int* in_sizes, int n_in,
                              void* d_out, int out_size)
{
    const float* x0 = (const float*)d_in[0];
    const float* x1 = (const float*)d_in[1];
    const float* x2 = (const float*)d_in[2];
    const float* s2 = (const float*)d_in[3];
    const float* q00_wih = (const float*)d_in[4];
    const float* q00_whh = (const float*)d_in[5];
    const float* q00_b   = (const float*)d_in[6];
    const float* q01_wih = (const float*)d_in[7];
    const float* q01_whh = (const float*)d_in[8];
    const float* q01_b   = (const float*)d_in[9];
    const float* i00_wih = (const float*)d_in[10];
    const float* i00_whh = (const float*)d_in[11];
    const float* i00_b   = (const float*)d_in[12];
    const float* i01_wih = (const float*)d_in[13];
    const float* i01_whh = (const float*)d_in[14];
    const float* i01_b   = (const float*)d_in[15];
    const float* i02_wih = (const float*)d_in[16];
    const float* i02_whh = (const float*)d_in[17];
    const float* i02_b   = (const float*)d_in[18];
    const float* q03_w = (const float*)d_in[19];
    const float* q03_b = (const float*)d_in[20];
    const float* q1_w  = (const float*)d_in[21];
    const float* q1_b  = (const float*)d_in[22];
    const float* q2_w  = (const float*)d_in[23];
    const float* q2_b  = (const float*)d_in[24];
    const float* i03_w = (const float*)d_in[25];
    const float* i03_b = (const float*)d_in[26];
    const float* i1_w  = (const float*)d_in[27];
    const float* i1_b  = (const float*)d_in[28];
    const float* i2_w  = (const float*)d_in[29];
    const float* i2_b  = (const float*)d_in[30];
    float* out = (float*)d_out;

    cudaFuncSetAttribute(lstm_mma_kernel, cudaFuncAttributeMaxDynamicSharedMemorySize, LSTM_SMEM_BYTES);
    cudaFuncSetAttribute(head_kernel, cudaFuncAttributeMaxDynamicSharedMemorySize, HEAD_SMEM_BYTES);

    dim3 grid(BB / MROWS, 6);   // 128 batch tiles x 6 LSTM runs = 768 CTAs, 2/SM
    lstm_mma_kernel<<<grid, 256, LSTM_SMEM_BYTES>>>(
        x0, x1, x2,
        q00_wih, q00_whh, q00_b,
        q01_wih, q01_whh, q01_b,
        i00_wih, i00_whh, i00_b,
        i01_wih, i01_whh, i01_b,
        i02_wih, i02_whh, i02_b);

    head_kernel<<<dim3(64, 2), 256, HEAD_SMEM_BYTES>>>(
        s2,
        q03_w, q03_b, q1_w, q1_b, q2_w, q2_b,
        i03_w, i03_b, i1_w, i1_b, i2_w, i2_b,
        out);
}

// round 9
// speedup vs baseline: 4.7040x; 1.0444x over previous
#include <cuda_runtime.h>
#include <cuda_fp16.h>

// Problem constants
#define HH    64
#define TT    32
#define BB    4096
#define AA    6
#define MROWS 32        // batch rows per lstm CTA

// lstm smem layout (bytes). Rows padded to 144B (72 halves) for conflict-free ldmatrix.
#define OFF_WS  0                    // Ws [256][72] half : weights fp16 (i/f/o pre-scaled 0.5)
#define OFF_HS  36864                // hs double buffer: 2 x [32][72] half
#define HS_BUF  4608                 // bytes per h buffer
#define OFF_WBS 46080                // float2[256] permuted {wih, b} (i/f/o scaled 0.5)
#define OFF_XS  48128                // float [32][33]
#define LSTM_SMEM_BYTES (OFF_XS + 32 * 33 * 4)   // 52352

// head kernel: 32 rows per CTA -> 108KB smem -> 2 CTAs/SM
#define HROWS 32
#define WT_STR 66
#define BUF_STR 260
#define QB_STR 66
#define HEAD_SMEM_FLOATS (256 * WT_STR + HROWS * BUF_STR + HROWS * QB_STR + HROWS * 8)
#define HEAD_SMEM_BYTES (HEAD_SMEM_FLOATS * 4)

// scratch: final hidden states, [B][192] (3 LSTM outputs per branch)
__device__ float g_hq[BB * 192];
__device__ float g_hi[BB * 192];

__device__ __forceinline__ float tanh_ap(float x) {
    float y;
    asm("tanh.approx.f32 %0, %1;" : "=f"(y) : "f"(x));
    return y;
}
__device__ __forceinline__ __half2 tanh2_ap(__half2 x) {
    __half2 y;
    asm("tanh.approx.f16x2 %0, %1;" : "=r"(*(unsigned*)&y) : "r"(*(unsigned*)&x));
    return y;
}

__device__ __forceinline__ unsigned smem_u32(const void* p) {
    unsigned a;
    asm("{ .reg .u64 t; cvta.to.shared.u64 t, %1; cvt.u32.u64 %0, t; }" : "=r"(a) : "l"(p));
    return a;
}
__device__ __forceinline__ void ldsm_x4(unsigned addr, unsigned& r0, unsigned& r1,
                                        unsigned& r2, unsigned& r3) {
    asm volatile("ldmatrix.sync.aligned.m8n8.x4.shared.b16 {%0,%1,%2,%3}, [%4];"
                 : "=r"(r0), "=r"(r1), "=r"(r2), "=r"(r3) : "r"(addr));
}
__device__ __forceinline__ void mma16816(float& d0, float& d1, float& d2, float& d3,
                                         unsigned a0, unsigned a1, unsigned a2, unsigned a3,
                                         unsigned b0, unsigned b1) {
    asm volatile(
        "mma.sync.aligned.m16n8k16.row.col.f32.f16.f16.f32 "
        "{%0,%1,%2,%3}, {%4,%5,%6,%7}, {%8,%9}, {%0,%1,%2,%3};"
        : "+f"(d0), "+f"(d1), "+f"(d2), "+f"(d3)
        : "r"(a0), "r"(a1), "r"(a2), "r"(a3), "r"(b0), "r"(b1));
}

// One CTA: 32 batch rows x one LSTM run. HMMA fp16 single-term recurrent GEMM.
// i/f/o gate weights pre-scaled by 0.5 so sigmoid(x) = 0.5*tanh(acc)+0.5 with
// no extra scale op. Intermediate steps use tanh.approx.f16x2 (row pairs packed)
// to halve MUFU traffic; the final step uses the fp32 tanh.approx path.
// h is double-buffered in smem -> one __syncthreads per step.
__global__ __launch_bounds__(256, 2) void lstm_mma_kernel(
    const float* __restrict__ x0, const float* __restrict__ x1, const float* __restrict__ x2,
    const float* __restrict__ q00_wih, const float* __restrict__ q00_whh, const float* __restrict__ q00_b,
    const float* __restrict__ q01_wih, const float* __restrict__ q01_whh, const float* __restrict__ q01_b,
    const float* __restrict__ i00_wih, const float* __restrict__ i00_whh, const float* __restrict__ i00_b,
    const float* __restrict__ i01_wih, const float* __restrict__ i01_whh, const float* __restrict__ i01_b,
    const float* __restrict__ i02_wih, const float* __restrict__ i02_whh, const float* __restrict__ i02_b)
{
    extern __shared__ char smem[];
    const unsigned sb = smem_u32(smem);

    const float* x; const float* wih; const float* whh; const float* bias;
    float* hout; int coloff;
    switch (blockIdx.y) {
        case 0:  x = x0; wih = q00_wih; whh = q00_whh; bias = q00_b; hout = g_hq; coloff = 0;   break;
        case 1:  x = x1; wih = q01_wih; whh = q01_whh; bias = q01_b; hout = g_hq; coloff = 64;  break;
        case 2:  x = x2; wih = q01_wih; whh = q01_whh; bias = q01_b; hout = g_hq; coloff = 128; break;
        case 3:  x = x0; wih = i00_wih; whh = i00_whh; bias = i00_b; hout = g_hi; coloff = 0;   break;
        case 4:  x = x1; wih = i01_wih; whh = i01_whh; bias = i01_b; hout = g_hi; coloff = 64;  break;
        default: x = x2; wih = i02_wih; whh = i02_whh; bias = i02_b; hout = g_hi; coloff = 128; break;
    }

    const int tid  = threadIdx.x;
    const int wid  = tid >> 5;
    const int lane = tid & 31;
    const int rg   = wid & 1;        // 16-row group
    const int gq   = wid >> 1;       // 64-gate quarter (0..3)
    const int g    = lane >> 2;
    const int tl   = lane & 3;
    const int r0g  = blockIdx.x * MROWS;

    // ---- stage whh fp16, permuted, 0.5-scaled for i/f/o (tg != 2) ----
    __half* ws = (__half*)(smem + OFF_WS);
    for (int idx = tid; idx < 256 * 64; idx += 256) {
        int go = idx >> 6, k = idx & 63;
        int tg = go >> 6, u = go & 63;
        int p  = (u & 3) * 2 + (tg & 1) + 8 * (tg >> 1) + 16 * (u >> 2);
        float sc = (tg == 2) ? 1.0f : 0.5f;
        ws[p * 72 + k] = __float2half(whh[idx] * sc);
    }
    // permuted {wih, b}, same 0.5 scale for i/f/o
    {
        int go = tid;
        int tg = go >> 6, u = go & 63;
        int p  = (u & 3) * 2 + (tg & 1) + 8 * (tg >> 1) + 16 * (u >> 2);
        float sc = (tg == 2) ? 1.0f : 0.5f;
        ((float2*)(smem + OFF_WBS))[p] = make_float2(wih[go] * sc, bias[go] * sc);
    }
    // x tile [32][33]
    float* xs = (float*)(smem + OFF_XS);
    for (int idx = tid; idx < MROWS * TT; idx += 256) {
        int r = idx >> 5, tt = idx & 31;
        xs[r * 33 + tt] = x[(size_t)(r0g + r) * TT + tt];
    }
    __syncthreads();

    // per-lane ldmatrix addresses
    const int rowA  = rg * 16 + (lane & 7) + 8 * ((lane >> 3) & 1);
    const unsigned aoff = (unsigned)(rowA * 144 + (lane >> 4) * 16);
    const int rowBb = gq * 64 + (lane & 7) + 8 * (lane >> 4);
    const unsigned boff = (unsigned)(rowBb * 144 + ((lane >> 3) & 1) * 16);

    const int r0 = rg * 16 + g;       // this thread's rows
    const int r1 = r0 + 8;

    float cst[8];
    #pragma unroll
    for (int i = 0; i < 8; ++i) cst[i] = 0.f;

    const float4* wbs4 = (const float4*)(smem + OFF_WBS);
    const __half2 hhalf = __floats2half2_rn(0.5f, 0.5f);

    float acc[32];

    #pragma unroll 1
    for (int t = 0; t < TT - 1; ++t) {
        #pragma unroll
        for (int i = 0; i < 32; ++i) acc[i] = 0.f;

        if (t > 0) {
            const unsigned rbase = sb + OFF_HS + ((unsigned)((t + 1) & 1)) * HS_BUF;
            #pragma unroll
            for (int kc = 0; kc < 4; ++kc) {
                unsigned ah0, ah1, ah2, ah3;
                ldsm_x4(rbase + aoff + kc * 32, ah0, ah1, ah2, ah3);
                #pragma unroll
                for (int np = 0; np < 4; ++np) {
                    unsigned bh0, bh1, bh2, bh3;
                    unsigned bb = boff + (unsigned)(np * 16 * 144 + kc * 32);
                    ldsm_x4(sb + OFF_WS + bb, bh0, bh1, bh2, bh3);
                    float* e = acc + np * 8;
                    mma16816(e[0], e[1], e[2], e[3], ah0, ah1, ah2, ah3, bh0, bh1);
                    mma16816(e[4], e[5], e[6], e[7], ah0, ah1, ah2, ah3, bh2, bh3);
                }
            }
        }

        // fast epilogue: f16x2 tanh, row pairs packed
        __half* hw = (__half*)(smem + OFF_HS + (t & 1) * HS_BUF);
        float xv0 = xs[r0 * 33 + t];
        float xv1 = xs[r1 * 33 + t];
        #pragma unroll
        for (int q = 0; q < 4; ++q) {
            int pq = 16 * (gq * 4 + q) + 2 * tl;
            float4 wif = wbs4[pq >> 1];          // (wih_i, b_i, wih_f, b_f) scaled
            float4 wgo = wbs4[(pq >> 1) + 4];    // (wih_g, b_g, wih_o, b_o)
            int u = 16 * gq + 4 * q + tl;
            float iv0 = acc[8 * q + 0] + fmaf(wif.x, xv0, wif.y);
            float fv0 = acc[8 * q + 1] + fmaf(wif.z, xv0, wif.w);
            float iv1 = acc[8 * q + 2] + fmaf(wif.x, xv1, wif.y);
            float fv1 = acc[8 * q + 3] + fmaf(wif.z, xv1, wif.w);
            float gv0 = acc[8 * q + 4] + fmaf(wgo.x, xv0, wgo.y);
            float ov0 = acc[8 * q + 5] + fmaf(wgo.z, xv0, wgo.w);
            float gv1 = acc[8 * q + 6] + fmaf(wgo.x, xv1, wgo.y);
            float ov1 = acc[8 * q + 7] + fmaf(wgo.z, xv1, wgo.w);

            __half2 ti2 = tanh2_ap(__floats2half2_rn(iv0, iv1));
            __half2 tf2 = tanh2_ap(__floats2half2_rn(fv0, fv1));
            __half2 tg2 = tanh2_ap(__floats2half2_rn(gv0, gv1));
            __half2 to2 = tanh2_ap(__floats2half2_rn(ov0, ov1));

            float2 ti = __half22float2(ti2);
            float2 tf = __half22float2(tf2);
            float2 tgf = __half22float2(tg2);
            float c0 = fmaf(0.5f, tf.x, 0.5f) * cst[2 * q] +
                       fmaf(0.5f, ti.x, 0.5f) * tgf.x;
            float c1 = fmaf(0.5f, tf.y, 0.5f) * cst[2 * q + 1] +
                       fmaf(0.5f, ti.y, 0.5f) * tgf.y;
            cst[2 * q] = c0;
            cst[2 * q + 1] = c1;
            __half2 tc2 = tanh2_ap(__floats2half2_rn(c0, c1));
            __half2 so2 = __hfma2(to2, hhalf, hhalf);
            __half2 h2v = __hmul2(so2, tc2);
            hw[r0 * 72 + u] = __low2half(h2v);
            hw[r1 * 72 + u] = __high2half(h2v);
        }
        __syncthreads();   // new h visible; prior reads complete
    }

    // ---- final step (t = TT-1): fp32-accurate epilogue ----
    {
        const int t = TT - 1;
        #pragma unroll
        for (int i = 0; i < 32; ++i) acc[i] = 0.f;
        const unsigned rbase = sb + OFF_HS + ((unsigned)((t + 1) & 1)) * HS_BUF;
        #pragma unroll
        for (int kc = 0; kc < 4; ++kc) {
            unsigned ah0, ah1, ah2, ah3;
            ldsm_x4(rbase + aoff + kc * 32, ah0, ah1, ah2, ah3);
            #pragma unroll
            for (int np = 0; np < 4; ++np) {
                unsigned bh0, bh1, bh2, bh3;
                unsigned bb = boff + (unsigned)(np * 16 * 144 + kc * 32);
                ldsm_x4(sb + OFF_WS + bb, bh0, bh1, bh2, bh3);
                float* e = acc + np * 8;
                mma16816(e[0], e[1], e[2], e[3], ah0, ah1, ah2, ah3, bh0, bh1);
                mma16816(e[4], e[5], e[6], e[7], ah0, ah1, ah2, ah3, bh2, bh3);
            }
        }
        float xv0 = xs[r0 * 33 + t];
        float xv1 = xs[r1 * 33 + t];
        #pragma unroll
        for (int q = 0; q < 4; ++q) {
            int pq = 16 * (gq * 4 + q) + 2 * tl;
            float4 wif = wbs4[pq >> 1];
            float4 wgo = wbs4[(pq >> 1) + 4];
            int u = 16 * gq + 4 * q + tl;
            #pragma unroll
            for (int rowj = 0; rowj < 2; ++rowj) {
                float xv = rowj ? xv1 : xv0;
                float iv = acc[8 * q + rowj * 2 + 0] + fmaf(wif.x, xv, wif.y);
                float fv = acc[8 * q + rowj * 2 + 1] + fmaf(wif.z, xv, wif.w);
                float gv = acc[8 * q + 4 + rowj * 2 + 0] + fmaf(wgo.x, xv, wgo.y);
                float ov = acc[8 * q + 4 + rowj * 2 + 1] + fmaf(wgo.z, xv, wgo.w);
                // weights pre-scaled: sigmoid(x) = 0.5*tanh(acc)+0.5
                float si = fmaf(0.5f, tanh_ap(iv), 0.5f);
                float sf = fmaf(0.5f, tanh_ap(fv), 0.5f);
                float so = fmaf(0.5f, tanh_ap(ov), 0.5f);
                float cc = sf * cst[q * 2 + rowj] + si * tanh_ap(gv);
                float h = so * tanh_ap(cc);
                int row = rowj ? r1 : r0;
                hout[(size_t)(r0g + row) * 192 + coloff + u] = h;
            }
        }
    }
}

// Head: grid (128, 2): 32 rows per CTA (2 CTAs/SM), w1 staged transposed in smem.
__global__ __launch_bounds__(256) void head_kernel(
    const float* __restrict__ s2,
    const float* __restrict__ q03_w, const float* __restrict__ q03_b,
    const float* __restrict__ q1_w,  const float* __restrict__ q1_b,
    const float* __restrict__ q2_w,  const float* __restrict__ q2_b,
    const float* __restrict__ i03_w, const float* __restrict__ i03_b,
    const float* __restrict__ i1_w,  const float* __restrict__ i1_b,
    const float* __restrict__ i2_w,  const float* __restrict__ i2_b,
    float* __restrict__ out)
{
    extern __shared__ float hs[];
    float* wt  = hs;                          // [256][WT_STR]
    float* buf = wt + 256 * WT_STR;           // [HROWS][BUF_STR]
    float* qb  = buf + HROWS * BUF_STR;       // [HROWS][QB_STR]
    float* ib  = qb + HROWS * QB_STR;         // [HROWS][8]

    const int tid  = threadIdx.x;
    const int gi   = tid & 31;
    const int ri   = tid >> 5;
    const int row0 = blockIdx.x * HROWS;
    const int br   = blockIdx.y;

    const float* gh  = br ? g_hi  : g_hq;
    const float* w03 = br ? i03_w : q03_w;
    const float* b03 = br ? i03_b : q03_b;
    const float* w1  = br ? i1_w  : q1_w;
    const float* b1  = br ? i1_b  : q1_b;
    const float* w2  = br ? i2_w  : q2_w;
    const float* b2  = br ? i2_b  : q2_b;

    for (int idx = tid; idx < 64 * 256; idx += 256) {
        int u = idx >> 8, k = idx & 255;
        wt[k * WT_STR + u] = w1[idx];
    }
    for (int idx = tid; idx < HROWS * 192; idx += 256) {
        int r = idx / 192, k = idx - r * 192;
        buf[r * BUF_STR + k] = gh[(row0 + r) * 192 + k];
    }
    for (int idx = tid; idx < HROWS * 64; idx += 256) {
        int r = idx >> 6, u = idx & 63;
        const float* s = &s2[(row0 + r) * 3];
        float a = b03[u] + s[0] * w03[u * 3] + s[1] * w03[u * 3 + 1] + s[2] * w03[u * 3 + 2];
        buf[r * BUF_STR + 192 + u] = fmaxf(a, 0.f);
    }
    __syncthreads();

    // register-tiled GEMV: thread (gi,ri) -> rows ri*4..+3, outs gi*2..+1
    float a0[4], a1[4];
    {
        float bb0 = b1[gi * 2], bb1 = b1[gi * 2 + 1];
        #pragma unroll
        for (int r = 0; r < 4; ++r) { a0[r] = bb0; a1[r] = bb1; }
    }
    #pragma unroll 8
    for (int k = 0; k < 256; ++k) {
        float2 wv = *(const float2*)&wt[k * WT_STR + gi * 2];
        #pragma unroll
        for (int r = 0; r < 4; ++r) {
            float hv = buf[(ri * 4 + r) * BUF_STR + k];
            a0[r] = fmaf(hv, wv.x, a0[r]);
            a1[r] = fmaf(hv, wv.y, a1[r]);
        }
    }
    #pragma unroll
    for (int r = 0; r < 4; ++r)
        *(float2*)&qb[(ri * 4 + r) * QB_STR + gi * 2] =
            make_float2(fmaxf(a0[r], 0.f), fmaxf(a1[r], 0.f));
    __syncthreads();

    for (int it = tid; it < HROWS * AA; it += 256) {
        int r = it / AA;
        int a = it - r * AA;
        float acc = b2[a];
        #pragma unroll 8
        for (int k = 0; k < 64; ++k)
            acc = fmaf(w2[a * 64 + k], qb[r * QB_STR + k], acc);
        if (br == 0) out[(row0 + r) * AA + a] = acc;        // q (no relu)
        else         ib[r * 8 + a] = fmaxf(acc, 0.f);       // i vec
    }
    if (br == 1) {
        __syncthreads();
        if (tid < HROWS) {
            int r = tid;
            float m = ib[r * 8];
            #pragma unroll
            for (int j = 1; j < AA; ++j) m = fmaxf(m, ib[r * 8 + j]);
            float s = 0.f;
            #pragma unroll
            for (int j = 0; j < AA; ++j) s += __expf(ib[r * 8 + j] - m);
            float lse = m + __logf(s);
            #pragma unroll
            for (int j = 0; j < AA; ++j) {
                float iv = ib[r * 8 + j];
                out[BB * AA + (row0 + r) * AA + j]     = iv - lse;
                out[2 * BB * AA + (row0 + r) * AA + j] = iv;
            }
        }
    }
}

extern "C" void kernel_launch(void* const* d_in, const int* in_sizes, int n_in,
                              void* d_out, int out_size)
{
    const float* x0 = (const float*)d_in[0];
    const float* x1 = (const float*)d_in[1];
    const float* x2 = (const float*)d_in[2];
    const float* s2 = (const float*)d_in[3];
    const float* q00_wih = (const float*)d_in[4];
    const float* q00_whh = (const float*)d_in[5];
    const float* q00_b   = (const float*)d_in[6];
    const float* q01_wih = (const float*)d_in[7];
    const float* q01_whh = (const float*)d_in[8];
    const float* q01_b   = (const float*)d_in[9];
    const float* i00_wih = (const float*)d_in[10];
    const float* i00_whh = (const float*)d_in[11];
    const float* i00_b   = (const float*)d_in[12];
    const float* i01_wih = (const float*)d_in[13];
    const float* i01_whh = (const float*)d_in[14];
    const float* i01_b   = (const float*)d_in[15];
    const float* i02_wih = (const float*)d_in[16];
    const float* i02_whh = (const float*)d_in[17];
    const float* i02_b   = (const float*)d_in[18];
    const float* q03_w = (const float*)d_in[19];
    const float* q03_b = (const float*)d_in[20];
    const float* q1_w  = (const float*)d_in[21];
    const float* q1_b  = (const float*)d_in[22];
    const float* q2_w  = (const float*)d_in[23];
    const float* q2_b  = (const float*)d_in[24];
    const float* i03_w = (const float*)d_in[25];
    const float* i03_b = (const float*)d_in[26];
    const float* i1_w  = (const float*)d_in[27];
    const float* i1_b  = (const float*)d_in[28];
    const float* i2_w  = (const float*)d_in[29];
    const float* i2_b  = (const float*)d_in[30];
    float* out = (float*)d_out;

    cudaFuncSetAttribute(lstm_mma_kernel, cudaFuncAttributeMaxDynamicSharedMemorySize, LSTM_SMEM_BYTES);
    cudaFuncSetAttribute(head_kernel, cudaFuncAttributeMaxDynamicSharedMemorySize, HEAD_SMEM_BYTES);

    dim3 grid(BB / MROWS, 6);   // 128 batch tiles x 6 LSTM runs = 768 CTAs, 2/SM
    lstm_mma_kernel<<<grid, 256, LSTM_SMEM_BYTES>>>(
        x0, x1, x2,
        q00_wih, q00_whh, q00_b,
        q01_wih, q01_whh, q01_b,
        i00_wih, i00_whh, i00_b,
        i01_wih, i01_whh, i01_b,
        i02_wih, i02_whh, i02_b);

    head_kernel<<<dim3(BB / HROWS, 2), 256, HEAD_SMEM_BYTES>>>(
        s2,
        q03_w, q03_b, q1_w, q1_b, q2_w, q2_b,
        i03_w, i03_b, i1_w, i1_b, i2_w, i2_b,
        out);
}

// round 10
// speedup vs baseline: 5.6042x; 1.1914x over previous
#include <cuda_runtime.h>
#include <cuda_fp16.h>

// Problem constants
#define HH    64
#define TT    32
#define BB    4096
#define AA    6
#define MROWS 32        // batch rows per lstm CTA

// lstm smem layout (bytes). Rows padded to 144B (72 halves) for conflict-free ldmatrix.
#define OFF_WS  0                    // Ws [256][72] half : weights fp16 (i/f/o pre-scaled 0.5)
#define OFF_HS  36864                // hs double buffer: 2 x [32][72] half
#define HS_BUF  4608                 // bytes per h buffer
#define OFF_WBS 46080                // float2[256] permuted {wih, b} (i/f/o scaled 0.5)
#define OFF_XS  48128                // float [32][33]
#define LSTM_SMEM_BYTES (OFF_XS + 32 * 33 * 4)   // 52352

// head kernel: 32 rows per CTA -> 2 CTAs/SM
#define HROWS 32
#define WT_STR 66
#define BUF_STR 260
#define QB_STR 66
#define HEAD_SMEM_FLOATS (256 * WT_STR + HROWS * BUF_STR + HROWS * QB_STR + HROWS * 8)
#define HEAD_SMEM_BYTES (HEAD_SMEM_FLOATS * 4)

// scratch: final hidden states, [B][192] (3 LSTM outputs per branch)
__device__ float g_hq[BB * 192];
__device__ float g_hi[BB * 192];

__device__ __forceinline__ float tanh_ap(float x) {
    float y;
    asm("tanh.approx.f32 %0, %1;" : "=f"(y) : "f"(x));
    return y;
}
__device__ __forceinline__ __half2 tanh2_ap(__half2 x) {
    __half2 y;
    asm("tanh.approx.f16x2 %0, %1;" : "=r"(*(unsigned*)&y) : "r"(*(unsigned*)&x));
    return y;
}

__device__ __forceinline__ unsigned smem_u32(const void* p) {
    unsigned a;
    asm("{ .reg .u64 t; cvta.to.shared.u64 t, %1; cvt.u32.u64 %0, t; }" : "=r"(a) : "l"(p));
    return a;
}
__device__ __forceinline__ void ldsm_x4(unsigned addr, unsigned& r0, unsigned& r1,
                                        unsigned& r2, unsigned& r3) {
    asm volatile("ldmatrix.sync.aligned.m8n8.x4.shared.b16 {%0,%1,%2,%3}, [%4];"
                 : "=r"(r0), "=r"(r1), "=r"(r2), "=r"(r3) : "r"(addr));
}
__device__ __forceinline__ void mma16816(float& d0, float& d1, float& d2, float& d3,
                                         unsigned a0, unsigned a1, unsigned a2, unsigned a3,
                                         unsigned b0, unsigned b1) {
    asm volatile(
        "mma.sync.aligned.m16n8k16.row.col.f32.f16.f16.f32 "
        "{%0,%1,%2,%3}, {%4,%5,%6,%7}, {%8,%9}, {%0,%1,%2,%3};"
        : "+f"(d0), "+f"(d1), "+f"(d2), "+f"(d3)
        : "r"(a0), "r"(a1), "r"(a2), "r"(a3), "r"(b0), "r"(b1));
}
__device__ __forceinline__ void bar_group(int id) {
    asm volatile("bar.sync %0, 128;" :: "r"(id) : "memory");
}

// One CTA: 32 batch rows x one LSTM run. HMMA fp16 single-term recurrent GEMM.
// i/f/o weights pre-scaled 0.5 so sigmoid(x)=0.5*tanh(acc)+0.5. Epilogue is
// full half2 (tanh.approx.f16x2, HFMA2 cell update, fp16 c state); final step
// uses the fp32 path. The two 16-row halves (rg) of the CTA are independent,
// synced by per-group named barriers so they can drift into MMA/epi overlap.
// Half the static weight fragments are hoisted into registers.
__global__ __launch_bounds__(256, 2) void lstm_mma_kernel(
    const float* __restrict__ x0, const float* __restrict__ x1, const float* __restrict__ x2,
    const float* __restrict__ q00_wih, const float* __restrict__ q00_whh, const float* __restrict__ q00_b,
    const float* __restrict__ q01_wih, const float* __restrict__ q01_whh, const float* __restrict__ q01_b,
    const float* __restrict__ i00_wih, const float* __restrict__ i00_whh, const float* __restrict__ i00_b,
    const float* __restrict__ i01_wih, const float* __restrict__ i01_whh, const float* __restrict__ i01_b,
    const float* __restrict__ i02_wih, const float* __restrict__ i02_whh, const float* __restrict__ i02_b)
{
    extern __shared__ char smem[];
    const unsigned sb = smem_u32(smem);

    const float* x; const float* wih; const float* whh; const float* bias;
    float* hout; int coloff;
    switch (blockIdx.y) {
        case 0:  x = x0; wih = q00_wih; whh = q00_whh; bias = q00_b; hout = g_hq; coloff = 0;   break;
        case 1:  x = x1; wih = q01_wih; whh = q01_whh; bias = q01_b; hout = g_hq; coloff = 64;  break;
        case 2:  x = x2; wih = q01_wih; whh = q01_whh; bias = q01_b; hout = g_hq; coloff = 128; break;
        case 3:  x = x0; wih = i00_wih; whh = i00_whh; bias = i00_b; hout = g_hi; coloff = 0;   break;
        case 4:  x = x1; wih = i01_wih; whh = i01_whh; bias = i01_b; hout = g_hi; coloff = 64;  break;
        default: x = x2; wih = i02_wih; whh = i02_whh; bias = i02_b; hout = g_hi; coloff = 128; break;
    }

    const int tid  = threadIdx.x;
    const int wid  = tid >> 5;
    const int lane = tid & 31;
    const int rg   = wid & 1;        // 16-row group
    const int gq   = wid >> 1;       // 64-gate quarter (0..3)
    const int g    = lane >> 2;
    const int tl   = lane & 3;
    const int r0g  = blockIdx.x * MROWS;

    // ---- stage whh fp16, permuted, 0.5-scaled for i/f/o (tg != 2) ----
    __half* ws = (__half*)(smem + OFF_WS);
    for (int idx = tid; idx < 256 * 64; idx += 256) {
        int go = idx >> 6, k = idx & 63;
        int tg = go >> 6, u = go & 63;
        int p  = (u & 3) * 2 + (tg & 1) + 8 * (tg >> 1) + 16 * (u >> 2);
        float sc = (tg == 2) ? 1.0f : 0.5f;
        ws[p * 72 + k] = __float2half(whh[idx] * sc);
    }
    // permuted {wih, b}, same 0.5 scale for i/f/o
    {
        int go = tid;
        int tg = go >> 6, u = go & 63;
        int p  = (u & 3) * 2 + (tg & 1) + 8 * (tg >> 1) + 16 * (u >> 2);
        float sc = (tg == 2) ? 1.0f : 0.5f;
        ((float2*)(smem + OFF_WBS))[p] = make_float2(wih[go] * sc, bias[go] * sc);
    }
    // x tile [32][33]
    float* xs = (float*)(smem + OFF_XS);
    for (int idx = tid; idx < MROWS * TT; idx += 256) {
        int r = idx >> 5, tt = idx & 31;
        xs[r * 33 + tt] = x[(size_t)(r0g + r) * TT + tt];
    }
    __syncthreads();

    // per-lane ldmatrix addresses
    const int rowA  = rg * 16 + (lane & 7) + 8 * ((lane >> 3) & 1);
    const unsigned aoff = (unsigned)(rowA * 144 + (lane >> 4) * 16);
    const int rowBb = gq * 64 + (lane & 7) + 8 * (lane >> 4);
    const unsigned boff = (unsigned)(rowBb * 144 + ((lane >> 3) & 1) * 16);

    const int r0 = rg * 16 + g;       // this thread's rows
    const int r1 = r0 + 8;

    // hoist B fragments for kc = 0,1 into registers (static weights)
    unsigned bw[8][4];
    #pragma unroll
    for (int kc = 0; kc < 2; ++kc)
        #pragma unroll
        for (int np = 0; np < 4; ++np)
            ldsm_x4(sb + OFF_WS + boff + (unsigned)(np * 16 * 144 + kc * 32),
                    bw[kc * 4 + np][0], bw[kc * 4 + np][1],
                    bw[kc * 4 + np][2], bw[kc * 4 + np][3]);

    __half2 c2[4];
    #pragma unroll
    for (int i = 0; i < 4; ++i) c2[i] = __floats2half2_rn(0.f, 0.f);

    const float4* wbs4 = (const float4*)(smem + OFF_WBS);
    const __half2 hhalf = __floats2half2_rn(0.5f, 0.5f);
    const int barid = 1 + rg;

    float acc[32];

    #pragma unroll 1
    for (int t = 0; t < TT - 1; ++t) {
        #pragma unroll
        for (int i = 0; i < 32; ++i) acc[i] = 0.f;

        if (t > 0) {
            const unsigned rbase = sb + OFF_HS + ((unsigned)((t + 1) & 1)) * HS_BUF;
            #pragma unroll
            for (int kc = 0; kc < 4; ++kc) {
                unsigned ah0, ah1, ah2, ah3;
                ldsm_x4(rbase + aoff + kc * 32, ah0, ah1, ah2, ah3);
                #pragma unroll
                for (int np = 0; np < 4; ++np) {
                    unsigned b0, b1, b2, b3;
                    if (kc < 2) {
                        b0 = bw[kc * 4 + np][0]; b1 = bw[kc * 4 + np][1];
                        b2 = bw[kc * 4 + np][2]; b3 = bw[kc * 4 + np][3];
                    } else {
                        ldsm_x4(sb + OFF_WS + boff + (unsigned)(np * 16 * 144 + kc * 32),
                                b0, b1, b2, b3);
                    }
                    float* e = acc + np * 8;
                    mma16816(e[0], e[1], e[2], e[3], ah0, ah1, ah2, ah3, b0, b1);
                    mma16816(e[4], e[5], e[6], e[7], ah0, ah1, ah2, ah3, b2, b3);
                }
            }
        }

        // half2 epilogue
        __half* hw = (__half*)(smem + OFF_HS + (t & 1) * HS_BUF);
        float xv0 = xs[r0 * 33 + t];
        float xv1 = xs[r1 * 33 + t];
        #pragma unroll
        for (int q = 0; q < 4; ++q) {
            int pq = 16 * (gq * 4 + q) + 2 * tl;
            float4 wif = wbs4[pq >> 1];          // (wih_i, b_i, wih_f, b_f) scaled
            float4 wgo = wbs4[(pq >> 1) + 4];    // (wih_g, b_g, wih_o, b_o)
            int u = 16 * gq + 4 * q + tl;
            float iv0 = acc[8 * q + 0] + fmaf(wif.x, xv0, wif.y);
            float fv0 = acc[8 * q + 1] + fmaf(wif.z, xv0, wif.w);
            float iv1 = acc[8 * q + 2] + fmaf(wif.x, xv1, wif.y);
            float fv1 = acc[8 * q + 3] + fmaf(wif.z, xv1, wif.w);
            float gv0 = acc[8 * q + 4] + fmaf(wgo.x, xv0, wgo.y);
            float ov0 = acc[8 * q + 5] + fmaf(wgo.z, xv0, wgo.w);
            float gv1 = acc[8 * q + 6] + fmaf(wgo.x, xv1, wgo.y);
            float ov1 = acc[8 * q + 7] + fmaf(wgo.z, xv1, wgo.w);

            __half2 ti2 = tanh2_ap(__floats2half2_rn(iv0, iv1));
            __half2 tf2 = tanh2_ap(__floats2half2_rn(fv0, fv1));
            __half2 tg2 = tanh2_ap(__floats2half2_rn(gv0, gv1));
            __half2 to2 = tanh2_ap(__floats2half2_rn(ov0, ov1));

            __half2 si2 = __hfma2(ti2, hhalf, hhalf);
            __half2 sf2 = __hfma2(tf2, hhalf, hhalf);
            __half2 so2 = __hfma2(to2, hhalf, hhalf);
            c2[q] = __hfma2(sf2, c2[q], __hmul2(si2, tg2));
            __half2 tc2 = tanh2_ap(c2[q]);
            __half2 h2v = __hmul2(so2, tc2);
            hw[r0 * 72 + u] = __low2half(h2v);
            hw[r1 * 72 + u] = __high2half(h2v);
        }
        bar_group(barid);   // group-local: new h visible; prior reads complete
    }

    // ---- final step (t = TT-1): fp32-accurate epilogue ----
    {
        const int t = TT - 1;
        #pragma unroll
        for (int i = 0; i < 32; ++i) acc[i] = 0.f;
        const unsigned rbase = sb + OFF_HS + ((unsigned)((t + 1) & 1)) * HS_BUF;
        #pragma unroll
        for (int kc = 0; kc < 4; ++kc) {
            unsigned ah0, ah1, ah2, ah3;
            ldsm_x4(rbase + aoff + kc * 32, ah0, ah1, ah2, ah3);
            #pragma unroll
            for (int np = 0; np < 4; ++np) {
                unsigned b0, b1, b2, b3;
                if (kc < 2) {
                    b0 = bw[kc * 4 + np][0]; b1 = bw[kc * 4 + np][1];
                    b2 = bw[kc * 4 + np][2]; b3 = bw[kc * 4 + np][3];
                } else {
                    ldsm_x4(sb + OFF_WS + boff + (unsigned)(np * 16 * 144 + kc * 32),
                            b0, b1, b2, b3);
                }
                float* e = acc + np * 8;
                mma16816(e[0], e[1], e[2], e[3], ah0, ah1, ah2, ah3, b0, b1);
                mma16816(e[4], e[5], e[6], e[7], ah0, ah1, ah2, ah3, b2, b3);
            }
        }
        float xv0 = xs[r0 * 33 + t];
        float xv1 = xs[r1 * 33 + t];
        #pragma unroll
        for (int q = 0; q < 4; ++q) {
            int pq = 16 * (gq * 4 + q) + 2 * tl;
            float4 wif = wbs4[pq >> 1];
            float4 wgo = wbs4[(pq >> 1) + 4];
            int u = 16 * gq + 4 * q + tl;
            float2 cf = __half22float2(c2[q]);
            #pragma unroll
            for (int rowj = 0; rowj < 2; ++rowj) {
                float xv = rowj ? xv1 : xv0;
                float iv = acc[8 * q + rowj * 2 + 0] + fmaf(wif.x, xv, wif.y);
                float fv = acc[8 * q + rowj * 2 + 1] + fmaf(wif.z, xv, wif.w);
                float gv = acc[8 * q + 4 + rowj * 2 + 0] + fmaf(wgo.x, xv, wgo.y);
                float ov = acc[8 * q + 4 + rowj * 2 + 1] + fmaf(wgo.z, xv, wgo.w);
                float si = fmaf(0.5f, tanh_ap(iv), 0.5f);
                float sf = fmaf(0.5f, tanh_ap(fv), 0.5f);
                float so = fmaf(0.5f, tanh_ap(ov), 0.5f);
                float cold = rowj ? cf.y : cf.x;
                float cc = sf * cold + si * tanh_ap(gv);
                float h = so * tanh_ap(cc);
                int row = rowj ? r1 : r0;
                hout[(size_t)(r0g + row) * 192 + coloff + u] = h;
            }
        }
    }
}

// Head: grid (128, 2): 32 rows per CTA (2 CTAs/SM), w1 staged transposed in smem.
__global__ __launch_bounds__(256) void head_kernel(
    const float* __restrict__ s2,
    const float* __restrict__ q03_w, const float* __restrict__ q03_b,
    const float* __restrict__ q1_w,  const float* __restrict__ q1_b,
    const float* __restrict__ q2_w,  const float* __restrict__ q2_b,
    const float* __restrict__ i03_w, const float* __restrict__ i03_b,
    const float* __restrict__ i1_w,  const float* __restrict__ i1_b,
    const float* __restrict__ i2_w,  const float* __restrict__ i2_b,
    float* __restrict__ out)
{
    extern __shared__ float hs[];
    float* wt  = hs;                          // [256][WT_STR]
    float* buf = wt + 256 * WT_STR;           // [HROWS][BUF_STR]
    float* qb  = buf + HROWS * BUF_STR;       // [HROWS][QB_STR]
    float* ib  = qb + HROWS * QB_STR;         // [HROWS][8]

    const int tid  = threadIdx.x;
    const int gi   = tid & 31;
    const int ri   = tid >> 5;
    const int row0 = blockIdx.x * HROWS;
    const int br   = blockIdx.y;

    const float* gh  = br ? g_hi  : g_hq;
    const float* w03 = br ? i03_w : q03_w;
    const float* b03 = br ? i03_b : q03_b;
    const float* w1  = br ? i1_w  : q1_w;
    const float* b1  = br ? i1_b  : q1_b;
    const float* w2  = br ? i2_w  : q2_w;
    const float* b2  = br ? i2_b  : q2_b;

    for (int idx = tid; idx < 64 * 256; idx += 256) {
        int u = idx >> 8, k = idx & 255;
        wt[k * WT_STR + u] = w1[idx];
    }
    for (int idx = tid; idx < HROWS * 192; idx += 256) {
        int r = idx / 192, k = idx - r * 192;
        buf[r * BUF_STR + k] = gh[(row0 + r) * 192 + k];
    }
    for (int idx = tid; idx < HROWS * 64; idx += 256) {
        int r = idx >> 6, u = idx & 63;
        const float* s = &s2[(row0 + r) * 3];
        float a = b03[u] + s[0] * w03[u * 3] + s[1] * w03[u * 3 + 1] + s[2] * w03[u * 3 + 2];
        buf[r * BUF_STR + 192 + u] = fmaxf(a, 0.f);
    }
    __syncthreads();

    float a0[4], a1[4];
    {
        float bb0 = b1[gi * 2], bb1 = b1[gi * 2 + 1];
        #pragma unroll
        for (int r = 0; r < 4; ++r) { a0[r] = bb0; a1[r] = bb1; }
    }
    #pragma unroll 8
    for (int k = 0; k < 256; ++k) {
        float2 wv = *(const float2*)&wt[k * WT_STR + gi * 2];
        #pragma unroll
        for (int r = 0; r < 4; ++r) {
            float hv = buf[(ri * 4 + r) * BUF_STR + k];
            a0[r] = fmaf(hv, wv.x, a0[r]);
            a1[r] = fmaf(hv, wv.y, a1[r]);
        }
    }
    #pragma unroll
    for (int r = 0; r < 4; ++r)
        *(float2*)&qb[(ri * 4 + r) * QB_STR + gi * 2] =
            make_float2(fmaxf(a0[r], 0.f), fmaxf(a1[r], 0.f));
    __syncthreads();

    for (int it = tid; it < HROWS * AA; it += 256) {
        int r = it / AA;
        int a = it - r * AA;
        float acc = b2[a];
        #pragma unroll 8
        for (int k = 0; k < 64; ++k)
            acc = fmaf(w2[a * 64 + k], qb[r * QB_STR + k], acc);
        if (br == 0) out[(row0 + r) * AA + a] = acc;        // q (no relu)
        else         ib[r * 8 + a] = fmaxf(acc, 0.f);       // i vec
    }
    if (br == 1) {
        __syncthreads();
        if (tid < HROWS) {
            int r = tid;
            float m = ib[r * 8];
            #pragma unroll
            for (int j = 1; j < AA; ++j) m = fmaxf(m, ib[r * 8 + j]);
            float s = 0.f;
            #pragma unroll
            for (int j = 0; j < AA; ++j) s += __expf(ib[r * 8 + j] - m);
            float lse = m + __logf(s);
            #pragma unroll
            for (int j = 0; j < AA; ++j) {
                float iv = ib[r * 8 + j];
                out[BB * AA + (row0 + r) * AA + j]     = iv - lse;
                out[2 * BB * AA + (row0 + r) * AA + j] = iv;
            }
        }
    }
}

extern "C" void kernel_launch(void* const* d_in, const int* in_sizes, int n_in,
                              void* d_out, int out_size)
{
    const float* x0 = (const float*)d_in[0];
    const float* x1 = (const float*)d_in[1];
    const float* x2 = (const float*)d_in[2];
    const float* s2 = (const float*)d_in[3];
    const float* q00_wih = (const float*)d_in[4];
    const float* q00_whh = (const float*)d_in[5];
    const float* q00_b   = (const float*)d_in[6];
    const float* q01_wih = (const float*)d_in[7];
    const float* q01_whh = (const float*)d_in[8];
    const float* q01_b   = (const float*)d_in[9];
    const float* i00_wih = (const float*)d_in[10];
    const float* i00_whh = (const float*)d_in[11];
    const float* i00_b   = (const float*)d_in[12];
    const float* i01_wih = (const float*)d_in[13];
    const float* i01_whh = (const float*)d_in[14];
    const float* i01_b   = (const float*)d_in[15];
    const float* i02_wih = (const float*)d_in[16];
    const float* i02_whh = (const float*)d_in[17];
    const float* i02_b   = (const float*)d_in[18];
    const float* q03_w = (const float*)d_in[19];
    const float* q03_b = (const float*)d_in[20];
    const float* q1_w  = (const float*)d_in[21];
    const float* q1_b  = (const float*)d_in[22];
    const float* q2_w  = (const float*)d_in[23];
    const float* q2_b  = (const float*)d_in[24];
    const float* i03_w = (const float*)d_in[25];
    const float* i03_b = (const float*)d_in[26];
    const float* i1_w  = (const float*)d_in[27];
    const float* i1_b  = (const float*)d_in[28];
    const float* i2_w  = (const float*)d_in[29];
    const float* i2_b  = (const float*)d_in[30];
    float* out = (float*)d_out;

    cudaFuncSetAttribute(lstm_mma_kernel, cudaFuncAttributeMaxDynamicSharedMemorySize, LSTM_SMEM_BYTES);
    cudaFuncSetAttribute(head_kernel, cudaFuncAttributeMaxDynamicSharedMemorySize, HEAD_SMEM_BYTES);

    dim3 grid(BB / MROWS, 6);   // 128 batch tiles x 6 LSTM runs = 768 CTAs, 2/SM
    lstm_mma_kernel<<<grid, 256, LSTM_SMEM_BYTES>>>(
        x0, x1, x2,
        q00_wih, q00_whh, q00_b,
        q01_wih, q01_whh, q01_b,
        i00_wih, i00_whh, i00_b,
        i01_wih, i01_whh, i01_b,
        i02_wih, i02_whh, i02_b);

    head_kernel<<<dim3(BB / HROWS, 2), 256, HEAD_SMEM_BYTES>>>(
        s2,
        q03_w, q03_b, q1_w, q1_b, q2_w, q2_b,
        i03_w, i03_b, i1_w, i1_b, i2_w, i2_b,
        out);
}

// round 11
// speedup vs baseline: 6.6164x; 1.1806x over previous
#include <cuda_runtime.h>
#include <cuda_fp16.h>

// Problem constants
#define HH    64
#define TT    32
#define BB    4096
#define AA    6
#define MROWS 32        // batch rows per lstm CTA

// lstm smem layout (bytes). Rows padded to 144B (72 halves) for conflict-free ldmatrix.
#define OFF_WS  0                    // Ws [256][72] half : weights fp16 (i/f/o pre-scaled 0.5)
#define OFF_HS  36864                // hs double buffer: 2 x [32][72] half
#define HS_BUF  4608                 // bytes per h buffer
#define OFF_WBS 46080                // float2[256] permuted {wih, b} (final step only)
#define OFF_XS  48128                // float [32][33]
#define LSTM_SMEM_BYTES (OFF_XS + 32 * 33 * 4)   // 52352

// head kernel: 32 rows per CTA -> 2 CTAs/SM
#define HROWS 32
#define WT_STR 66
#define BUF_STR 260
#define QB_STR 66
#define HEAD_SMEM_FLOATS (256 * WT_STR + HROWS * BUF_STR + HROWS * QB_STR + HROWS * 8)
#define HEAD_SMEM_BYTES (HEAD_SMEM_FLOATS * 4)

// scratch: final hidden states, [B][192] (3 LSTM outputs per branch)
__device__ float g_hq[BB * 192];
__device__ float g_hi[BB * 192];

__device__ __forceinline__ float tanh_ap(float x) {
    float y;
    asm("tanh.approx.f32 %0, %1;" : "=f"(y) : "f"(x));
    return y;
}
__device__ __forceinline__ __half2 tanh2_ap(__half2 x) {
    __half2 y;
    asm("tanh.approx.f16x2 %0, %1;" : "=r"(*(unsigned*)&y) : "r"(*(unsigned*)&x));
    return y;
}

__device__ __forceinline__ unsigned smem_u32(const void* p) {
    unsigned a;
    asm("{ .reg .u64 t; cvta.to.shared.u64 t, %1; cvt.u32.u64 %0, t; }" : "=r"(a) : "l"(p));
    return a;
}
__device__ __forceinline__ void ldsm_x4(unsigned addr, unsigned& r0, unsigned& r1,
                                        unsigned& r2, unsigned& r3) {
    asm volatile("ldmatrix.sync.aligned.m8n8.x4.shared.b16 {%0,%1,%2,%3}, [%4];"
                 : "=r"(r0), "=r"(r1), "=r"(r2), "=r"(r3) : "r"(addr));
}
// fp32-acc HMMA (final step)
__device__ __forceinline__ void mma16816(float& d0, float& d1, float& d2, float& d3,
                                         unsigned a0, unsigned a1, unsigned a2, unsigned a3,
                                         unsigned b0, unsigned b1) {
    asm volatile(
        "mma.sync.aligned.m16n8k16.row.col.f32.f16.f16.f32 "
        "{%0,%1,%2,%3}, {%4,%5,%6,%7}, {%8,%9}, {%0,%1,%2,%3};"
        : "+f"(d0), "+f"(d1), "+f"(d2), "+f"(d3)
        : "r"(a0), "r"(a1), "r"(a2), "r"(a3), "r"(b0), "r"(b1));
}
// fp16-acc HMMA, accumulate into d
__device__ __forceinline__ void mma_h_acc(unsigned& d0, unsigned& d1,
                                          unsigned a0, unsigned a1, unsigned a2, unsigned a3,
                                          unsigned b0, unsigned b1) {
    asm volatile(
        "mma.sync.aligned.m16n8k16.row.col.f16.f16.f16.f16 "
        "{%0,%1}, {%2,%3,%4,%5}, {%6,%7}, {%0,%1};"
        : "+r"(d0), "+r"(d1)
        : "r"(a0), "r"(a1), "r"(a2), "r"(a3), "r"(b0), "r"(b1));
}
// fp16-acc HMMA, C = 0 (no accumulator pre-zeroing needed)
__device__ __forceinline__ void mma_h_zero(unsigned& d0, unsigned& d1,
                                           unsigned a0, unsigned a1, unsigned a2, unsigned a3,
                                           unsigned b0, unsigned b1) {
    asm volatile(
        "mma.sync.aligned.m16n8k16.row.col.f16.f16.f16.f16 "
        "{%0,%1}, {%2,%3,%4,%5}, {%6,%7}, {%8,%8};"
        : "=r"(d0), "=r"(d1)
        : "r"(a0), "r"(a1), "r"(a2), "r"(a3), "r"(b0), "r"(b1), "r"(0u));
}
__device__ __forceinline__ void bar_group(int id) {
    asm volatile("bar.sync %0, 128;" :: "r"(id) : "memory");
}

// One CTA: 32 batch rows x one LSTM run. HMMA fp16 recurrent GEMM with fp16
// accumulators for intermediate steps (gates emerge as half2 (i,f)/(g,o) pairs
// -> pure-half2 epilogue, no packs, no fp32 folds, no acc zeroing). Final step
// uses fp32-acc MMA + fp32 epilogue. i/f/o weights pre-scaled 0.5 so
// sigmoid(x)=0.5*tanh(acc)+0.5. rg halves sync on named barriers.
__global__ __launch_bounds__(256, 2) void lstm_mma_kernel(
    const float* __restrict__ x0, const float* __restrict__ x1, const float* __restrict__ x2,
    const float* __restrict__ q00_wih, const float* __restrict__ q00_whh, const float* __restrict__ q00_b,
    const float* __restrict__ q01_wih, const float* __restrict__ q01_whh, const float* __restrict__ q01_b,
    const float* __restrict__ i00_wih, const float* __restrict__ i00_whh, const float* __restrict__ i00_b,
    const float* __restrict__ i01_wih, const float* __restrict__ i01_whh, const float* __restrict__ i01_b,
    const float* __restrict__ i02_wih, const float* __restrict__ i02_whh, const float* __restrict__ i02_b)
{
    extern __shared__ char smem[];
    const unsigned sb = smem_u32(smem);

    const float* x; const float* wih; const float* whh; const float* bias;
    float* hout; int coloff;
    switch (blockIdx.y) {
        case 0:  x = x0; wih = q00_wih; whh = q00_whh; bias = q00_b; hout = g_hq; coloff = 0;   break;
        case 1:  x = x1; wih = q01_wih; whh = q01_whh; bias = q01_b; hout = g_hq; coloff = 64;  break;
        case 2:  x = x2; wih = q01_wih; whh = q01_whh; bias = q01_b; hout = g_hq; coloff = 128; break;
        case 3:  x = x0; wih = i00_wih; whh = i00_whh; bias = i00_b; hout = g_hi; coloff = 0;   break;
        case 4:  x = x1; wih = i01_wih; whh = i01_whh; bias = i01_b; hout = g_hi; coloff = 64;  break;
        default: x = x2; wih = i02_wih; whh = i02_whh; bias = i02_b; hout = g_hi; coloff = 128; break;
    }

    const int tid  = threadIdx.x;
    const int wid  = tid >> 5;
    const int lane = tid & 31;
    const int rg   = wid & 1;        // 16-row group
    const int gq   = wid >> 1;       // 64-gate quarter (0..3)
    const int g    = lane >> 2;
    const int tl   = lane & 3;
    const int r0g  = blockIdx.x * MROWS;

    // ---- stage whh fp16, permuted, 0.5-scaled for i/f/o (tg != 2) ----
    __half* ws = (__half*)(smem + OFF_WS);
    for (int idx = tid; idx < 256 * 64; idx += 256) {
        int go = idx >> 6, k = idx & 63;
        int tg = go >> 6, u = go & 63;
        int p  = (u & 3) * 2 + (tg & 1) + 8 * (tg >> 1) + 16 * (u >> 2);
        float sc = (tg == 2) ? 1.0f : 0.5f;
        ws[p * 72 + k] = __float2half(whh[idx] * sc);
    }
    // permuted {wih, b} table (final fp32 step only), same 0.5 scale for i/f/o
    {
        int go = tid;
        int tg = go >> 6, u = go & 63;
        int p  = (u & 3) * 2 + (tg & 1) + 8 * (tg >> 1) + 16 * (u >> 2);
        float sc = (tg == 2) ? 1.0f : 0.5f;
        ((float2*)(smem + OFF_WBS))[p] = make_float2(wih[go] * sc, bias[go] * sc);
    }
    // x tile [32][33]
    float* xs = (float*)(smem + OFF_XS);
    for (int idx = tid; idx < MROWS * TT; idx += 256) {
        int r = idx >> 5, tt = idx & 31;
        xs[r * 33 + tt] = x[(size_t)(r0g + r) * TT + tt];
    }
    __syncthreads();

    // per-lane ldmatrix addresses
    const int rowA  = rg * 16 + (lane & 7) + 8 * ((lane >> 3) & 1);
    const unsigned aoff = (unsigned)(rowA * 144 + (lane >> 4) * 16);
    const int rowBb = gq * 64 + (lane & 7) + 8 * (lane >> 4);
    const unsigned boff = (unsigned)(rowBb * 144 + ((lane >> 3) & 1) * 16);

    const int r0 = rg * 16 + g;       // this thread's rows
    const int r1 = r0 + 8;

    // hoist B fragments for kc = 0,1 into registers (static weights)
    unsigned bw[8][4];
    #pragma unroll
    for (int kc = 0; kc < 2; ++kc)
        #pragma unroll
        for (int np = 0; np < 4; ++np)
            ldsm_x4(sb + OFF_WS + boff + (unsigned)(np * 16 * 144 + kc * 32),
                    bw[kc * 4 + np][0], bw[kc * 4 + np][1],
                    bw[kc * 4 + np][2], bw[kc * 4 + np][3]);

    // hoisted half2 fold constants: per q, unit u = 16gq + 4q + tl
    __half2 w_if2[4], b_if2[4], w_go2[4], b_go2[4];
    #pragma unroll
    for (int q = 0; q < 4; ++q) {
        int u = 16 * gq + 4 * q + tl;
        w_if2[q] = __floats2half2_rn(0.5f * wih[u], 0.5f * wih[64 + u]);
        b_if2[q] = __floats2half2_rn(0.5f * bias[u], 0.5f * bias[64 + u]);
        w_go2[q] = __floats2half2_rn(wih[128 + u], 0.5f * wih[192 + u]);
        b_go2[q] = __floats2half2_rn(bias[128 + u], 0.5f * bias[192 + u]);
    }

    __half2 c2[4];
    #pragma unroll
    for (int i = 0; i < 4; ++i) c2[i] = __floats2half2_rn(0.f, 0.f);

    const __half2 h05   = __floats2half2_rn(0.5f, 0.5f);
    const __half2 m1_05 = __floats2half2_rn(1.0f, 0.5f);   // (tg passthrough, so scale)
    const __half2 a0_05 = __floats2half2_rn(0.0f, 0.5f);
    const int barid = 1 + rg;

    // fp16 accumulators: per np, (i,f) pair rows {g, g+8} and (g,o) pair
    unsigned aif[4][2], ago[4][2];
    #pragma unroll
    for (int np = 0; np < 4; ++np) {
        aif[np][0] = aif[np][1] = 0u;
        ago[np][0] = ago[np][1] = 0u;
    }

    #pragma unroll 1
    for (int t = 0; t < TT - 1; ++t) {
        if (t > 0) {
            const unsigned rbase = sb + OFF_HS + ((unsigned)((t + 1) & 1)) * HS_BUF;
            #pragma unroll
            for (int kc = 0; kc < 4; ++kc) {
                unsigned ah0, ah1, ah2, ah3;
                ldsm_x4(rbase + aoff + kc * 32, ah0, ah1, ah2, ah3);
                #pragma unroll
                for (int np = 0; np < 4; ++np) {
                    unsigned b0, b1, b2, b3;
                    if (kc < 2) {
                        b0 = bw[kc * 4 + np][0]; b1 = bw[kc * 4 + np][1];
                        b2 = bw[kc * 4 + np][2]; b3 = bw[kc * 4 + np][3];
                    } else {
                        ldsm_x4(sb + OFF_WS + boff + (unsigned)(np * 16 * 144 + kc * 32),
                                b0, b1, b2, b3);
                    }
                    if (kc == 0) {
                        mma_h_zero(aif[np][0], aif[np][1], ah0, ah1, ah2, ah3, b0, b1);
                        mma_h_zero(ago[np][0], ago[np][1], ah0, ah1, ah2, ah3, b2, b3);
                    } else {
                        mma_h_acc(aif[np][0], aif[np][1], ah0, ah1, ah2, ah3, b0, b1);
                        mma_h_acc(ago[np][0], ago[np][1], ah0, ah1, ah2, ah3, b2, b3);
                    }
                }
            }
        }

        // pure-half2 epilogue
        __half* hw = (__half*)(smem + OFF_HS + (t & 1) * HS_BUF);
        __half2 xh0 = __half2half2(__float2half(xs[r0 * 33 + t]));
        __half2 xh1 = __half2half2(__float2half(xs[r1 * 33 + t]));
        #pragma unroll
        for (int q = 0; q < 4; ++q) {
            int u = 16 * gq + 4 * q + tl;
            __half2 if0 = __hadd2(*(__half2*)&aif[q][0], __hfma2(w_if2[q], xh0, b_if2[q]));
            __half2 if1 = __hadd2(*(__half2*)&aif[q][1], __hfma2(w_if2[q], xh1, b_if2[q]));
            __half2 go0 = __hadd2(*(__half2*)&ago[q][0], __hfma2(w_go2[q], xh0, b_go2[q]));
            __half2 go1 = __hadd2(*(__half2*)&ago[q][1], __hfma2(w_go2[q], xh1, b_go2[q]));

            __half2 sif0 = __hfma2(tanh2_ap(if0), h05, h05);    // (si, sf) row r0
            __half2 sif1 = __hfma2(tanh2_ap(if1), h05, h05);    // row r1
            __half2 gso0 = __hfma2(tanh2_ap(go0), m1_05, a0_05); // (tg, so) row r0
            __half2 gso1 = __hfma2(tanh2_ap(go1), m1_05, a0_05);

            __half2 si2 = __lows2half2(sif0, sif1);
            __half2 sf2 = __highs2half2(sif0, sif1);
            __half2 tg2 = __lows2half2(gso0, gso1);
            __half2 so2 = __highs2half2(gso0, gso1);
            c2[q] = __hfma2(sf2, c2[q], __hmul2(si2, tg2));
            __half2 h2v = __hmul2(so2, tanh2_ap(c2[q]));
            hw[r0 * 72 + u] = __low2half(h2v);
            hw[r1 * 72 + u] = __high2half(h2v);
        }
        bar_group(barid);   // group-local: new h visible; prior reads complete
    }

    // ---- final step (t = TT-1): fp32-acc MMA + fp32 epilogue ----
    {
        const int t = TT - 1;
        float acc[32];
        #pragma unroll
        for (int i = 0; i < 32; ++i) acc[i] = 0.f;
        const unsigned rbase = sb + OFF_HS + ((unsigned)((t + 1) & 1)) * HS_BUF;
        #pragma unroll
        for (int kc = 0; kc < 4; ++kc) {
            unsigned ah0, ah1, ah2, ah3;
            ldsm_x4(rbase + aoff + kc * 32, ah0, ah1, ah2, ah3);
            #pragma unroll
            for (int np = 0; np < 4; ++np) {
                unsigned b0, b1, b2, b3;
                if (kc < 2) {
                    b0 = bw[kc * 4 + np][0]; b1 = bw[kc * 4 + np][1];
                    b2 = bw[kc * 4 + np][2]; b3 = bw[kc * 4 + np][3];
                } else {
                    ldsm_x4(sb + OFF_WS + boff + (unsigned)(np * 16 * 144 + kc * 32),
                            b0, b1, b2, b3);
                }
                float* e = acc + np * 8;
                mma16816(e[0], e[1], e[2], e[3], ah0, ah1, ah2, ah3, b0, b1);
                mma16816(e[4], e[5], e[6], e[7], ah0, ah1, ah2, ah3, b2, b3);
            }
        }
        const float4* wbs4 = (const float4*)(smem + OFF_WBS);
        float xv0 = xs[r0 * 33 + t];
        float xv1 = xs[r1 * 33 + t];
        #pragma unroll
        for (int q = 0; q < 4; ++q) {
            int pq = 16 * (gq * 4 + q) + 2 * tl;
            float4 wif = wbs4[pq >> 1];
            float4 wgo = wbs4[(pq >> 1) + 4];
            int u = 16 * gq + 4 * q + tl;
            float2 cf = __half22float2(c2[q]);
            #pragma unroll
            for (int rowj = 0; rowj < 2; ++rowj) {
                float xv = rowj ? xv1 : xv0;
                float iv = acc[8 * q + rowj * 2 + 0] + fmaf(wif.x, xv, wif.y);
                float fv = acc[8 * q + rowj * 2 + 1] + fmaf(wif.z, xv, wif.w);
                float gv = acc[8 * q + 4 + rowj * 2 + 0] + fmaf(wgo.x, xv, wgo.y);
                float ov = acc[8 * q + 4 + rowj * 2 + 1] + fmaf(wgo.z, xv, wgo.w);
                float si = fmaf(0.5f, tanh_ap(iv), 0.5f);
                float sf = fmaf(0.5f, tanh_ap(fv), 0.5f);
                float so = fmaf(0.5f, tanh_ap(ov), 0.5f);
                float cold = rowj ? cf.y : cf.x;
                float cc = sf * cold + si * tanh_ap(gv);
                float h = so * tanh_ap(cc);
                int row = rowj ? r1 : r0;
                hout[(size_t)(r0g + row) * 192 + coloff + u] = h;
            }
        }
    }
}

// Head: grid (128, 2): 32 rows per CTA (2 CTAs/SM), w1 staged transposed in smem.
// k-loop uses float4 buf broadcasts: ~3 smem phases/k vs 6 (was LDS-crossbar-bound).
__global__ __launch_bounds__(256) void head_kernel(
    const float* __restrict__ s2,
    const float* __restrict__ q03_w, const float* __restrict__ q03_b,
    const float* __restrict__ q1_w,  const float* __restrict__ q1_b,
    const float* __restrict__ q2_w,  const float* __restrict__ q2_b,
    const float* __restrict__ i03_w, const float* __restrict__ i03_b,
    const float* __restrict__ i1_w,  const float* __restrict__ i1_b,
    const float* __restrict__ i2_w,  const float* __restrict__ i2_b,
    float* __restrict__ out)
{
    extern __shared__ float hs[];
    float* wt  = hs;                          // [256][WT_STR]
    float* buf = wt + 256 * WT_STR;           // [HROWS][BUF_STR]
    float* qb  = buf + HROWS * BUF_STR;       // [HROWS][QB_STR]
    float* ib  = qb + HROWS * QB_STR;         // [HROWS][8]

    const int tid  = threadIdx.x;
    const int gi   = tid & 31;
    const int ri   = tid >> 5;
    const int row0 = blockIdx.x * HROWS;
    const int br   = blockIdx.y;

    const float* gh  = br ? g_hi  : g_hq;
    const float* w03 = br ? i03_w : q03_w;
    const float* b03 = br ? i03_b : q03_b;
    const float* w1  = br ? i1_w  : q1_w;
    const float* b1  = br ? i1_b  : q1_b;
    const float* w2  = br ? i2_w  : q2_w;
    const float* b2  = br ? i2_b  : q2_b;

    for (int idx = tid; idx < 64 * 256; idx += 256) {
        int u = idx >> 8, k = idx & 255;
        wt[k * WT_STR + u] = w1[idx];
    }
    for (int idx = tid; idx < HROWS * 192; idx += 256) {
        int r = idx / 192, k = idx - r * 192;
        buf[r * BUF_STR + k] = gh[(row0 + r) * 192 + k];
    }
    for (int idx = tid; idx < HROWS * 64; idx += 256) {
        int r = idx >> 6, u = idx & 63;
        const float* s = &s2[(row0 + r) * 3];
        float a = b03[u] + s[0] * w03[u * 3] + s[1] * w03[u * 3 + 1] + s[2] * w03[u * 3 + 2];
        buf[r * BUF_STR + 192 + u] = fmaxf(a, 0.f);
    }
    __syncthreads();

    float a0[4], a1[4];
    {
        float bb0 = b1[gi * 2], bb1 = b1[gi * 2 + 1];
        #pragma unroll
        for (int r = 0; r < 4; ++r) { a0[r] = bb0; a1[r] = bb1; }
    }
    #pragma unroll 2
    for (int k4 = 0; k4 < 256; k4 += 4) {
        float4 hv[4];
        #pragma unroll
        for (int r = 0; r < 4; ++r)
            hv[r] = *(const float4*)&buf[(ri * 4 + r) * BUF_STR + k4];
        #pragma unroll
        for (int kk = 0; kk < 4; ++kk) {
            float2 wv = *(const float2*)&wt[(k4 + kk) * WT_STR + gi * 2];
            #pragma unroll
            for (int r = 0; r < 4; ++r) {
                float hvv = ((const float*)&hv[r])[kk];
                a0[r] = fmaf(hvv, wv.x, a0[r]);
                a1[r] = fmaf(hvv, wv.y, a1[r]);
            }
        }
    }
    #pragma unroll
    for (int r = 0; r < 4; ++r)
        *(float2*)&qb[(ri * 4 + r) * QB_STR + gi * 2] =
            make_float2(fmaxf(a0[r], 0.f), fmaxf(a1[r], 0.f));
    __syncthreads();

    for (int it = tid; it < HROWS * AA; it += 256) {
        int r = it / AA;
        int a = it - r * AA;
        float acc = b2[a];
        #pragma unroll 8
        for (int k = 0; k < 64; ++k)
            acc = fmaf(w2[a * 64 + k], qb[r * QB_STR + k], acc);
        if (br == 0) out[(row0 + r) * AA + a] = acc;        // q (no relu)
        else         ib[r * 8 + a] = fmaxf(acc, 0.f);       // i vec
    }
    if (br == 1) {
        __syncthreads();
        if (tid < HROWS) {
            int r = tid;
            float m = ib[r * 8];
            #pragma unroll
            for (int j = 1; j < AA; ++j) m = fmaxf(m, ib[r * 8 + j]);
            float s = 0.f;
            #pragma unroll
            for (int j = 0; j < AA; ++j) s += __expf(ib[r * 8 + j] - m);
            float lse = m + __logf(s);
            #pragma unroll
            for (int j = 0; j < AA; ++j) {
                float iv = ib[r * 8 + j];
                out[BB * AA + (row0 + r) * AA + j]     = iv - lse;
                out[2 * BB * AA + (row0 + r) * AA + j] = iv;
            }
        }
    }
}

extern "C" void kernel_launch(void* const* d_in, const int* in_sizes, int n_in,
                              void* d_out, int out_size)
{
    const float* x0 = (const float*)d_in[0];
    const float* x1 = (const float*)d_in[1];
    const float* x2 = (const float*)d_in[2];
    const float* s2 = (const float*)d_in[3];
    const float* q00_wih = (const float*)d_in[4];
    const float* q00_whh = (const float*)d_in[5];
    const float* q00_b   = (const float*)d_in[6];
    const float* q01_wih = (const float*)d_in[7];
    const float* q01_whh = (const float*)d_in[8];
    const float* q01_b   = (const float*)d_in[9];
    const float* i00_wih = (const float*)d_in[10];
    const float* i00_whh = (const float*)d_in[11];
    const float* i00_b   = (const float*)d_in[12];
    const float* i01_wih = (const float*)d_in[13];
    const float* i01_whh = (const float*)d_in[14];
    const float* i01_b   = (const float*)d_in[15];
    const float* i02_wih = (const float*)d_in[16];
    const float* i02_whh = (const float*)d_in[17];
    const float* i02_b   = (const float*)d_in[18];
    const float* q03_w = (const float*)d_in[19];
    const float* q03_b = (const float*)d_in[20];
    const float* q1_w  = (const float*)d_in[21];
    const float* q1_b  = (const float*)d_in[22];
    const float* q2_w  = (const float*)d_in[23];
    const float* q2_b  = (const float*)d_in[24];
    const float* i03_w = (const float*)d_in[25];
    const float* i03_b = (const float*)d_in[26];
    const float* i1_w  = (const float*)d_in[27];
    const float* i1_b  = (const float*)d_in[28];
    const float* i2_w  = (const float*)d_in[29];
    const float* i2_b  = (const float*)d_in[30];
    float* out = (float*)d_out;

    cudaFuncSetAttribute(lstm_mma_kernel, cudaFuncAttributeMaxDynamicSharedMemorySize, LSTM_SMEM_BYTES);
    cudaFuncSetAttribute(head_kernel, cudaFuncAttributeMaxDynamicSharedMemorySize, HEAD_SMEM_BYTES);

    dim3 grid(BB / MROWS, 6);   // 128 batch tiles x 6 LSTM runs = 768 CTAs, 2/SM
    lstm_mma_kernel<<<grid, 256, LSTM_SMEM_BYTES>>>(
        x0, x1, x2,
        q00_wih, q00_whh, q00_b,
        q01_wih, q01_whh, q01_b,
        i00_wih, i00_whh, i00_b,
        i01_wih, i01_whh, i01_b,
        i02_wih, i02_whh, i02_b);

    head_kernel<<<dim3(BB / HROWS, 2), 256, HEAD_SMEM_BYTES>>>(
        s2,
        q03_w, q03_b, q1_w, q1_b, q2_w, q2_b,
        i03_w, i03_b, i1_w, i1_b, i2_w, i2_b,
        out);
}

// round 12
// speedup vs baseline: 6.8368x; 1.0333x over previous
#include <cuda_runtime.h>
#include <cuda_fp16.h>

// Problem constants
#define HH    64
#define TT    32
#define BB    4096
#define AA    6
#define MROWS 32        // batch rows per lstm CTA

// lstm smem layout (bytes). Rows padded to 144B (72 halves) for conflict-free ldmatrix.
#define OFF_WS  0                    // Ws [256][72] half : weights fp16 (i/f/o pre-scaled 0.5)
#define OFF_HS  36864                // hs double buffer: 2 x [32][72] half
#define HS_BUF  4608                 // bytes per h buffer
#define OFF_WBS 46080                // float2[256] permuted {wih, b} (final step only)
#define OFF_XS  48128                // float [32][33]
#define LSTM_SMEM_BYTES (OFF_XS + 32 * 33 * 4)   // 52352

// head kernel v2 (HMMA): 64 rows x 1 branch per CTA, grid (64, 2) = 128 CTAs.
// A = concat [64][256] fp16 (row stride 264 halves = 528B), B = w1 [64][256] fp16.
#define H_AH 0                       // A fp16 [64][264]
#define H_BH 33792                   // B fp16 [64][264]
#define H_QB 67584                   // qb fp32 [64][66]
#define H_IB 84480                   // ib fp32 [64][8]
#define HEAD_SMEM_BYTES (H_IB + 2048)

// scratch: final hidden states, [B][192] (3 LSTM outputs per branch)
__device__ float g_hq[BB * 192];
__device__ float g_hi[BB * 192];

__device__ __forceinline__ float tanh_ap(float x) {
    float y;
    asm("tanh.approx.f32 %0, %1;" : "=f"(y) : "f"(x));
    return y;
}
__device__ __forceinline__ __half2 tanh2_ap(__half2 x) {
    __half2 y;
    asm("tanh.approx.f16x2 %0, %1;" : "=r"(*(unsigned*)&y) : "r"(*(unsigned*)&x));
    return y;
}

__device__ __forceinline__ unsigned smem_u32(const void* p) {
    unsigned a;
    asm("{ .reg .u64 t; cvta.to.shared.u64 t, %1; cvt.u32.u64 %0, t; }" : "=r"(a) : "l"(p));
    return a;
}
__device__ __forceinline__ void ldsm_x4(unsigned addr, unsigned& r0, unsigned& r1,
                                        unsigned& r2, unsigned& r3) {
    asm volatile("ldmatrix.sync.aligned.m8n8.x4.shared.b16 {%0,%1,%2,%3}, [%4];"
                 : "=r"(r0), "=r"(r1), "=r"(r2), "=r"(r3) : "r"(addr));
}
// fp32-acc HMMA
__device__ __forceinline__ void mma16816(float& d0, float& d1, float& d2, float& d3,
                                         unsigned a0, unsigned a1, unsigned a2, unsigned a3,
                                         unsigned b0, unsigned b1) {
    asm volatile(
        "mma.sync.aligned.m16n8k16.row.col.f32.f16.f16.f32 "
        "{%0,%1,%2,%3}, {%4,%5,%6,%7}, {%8,%9}, {%0,%1,%2,%3};"
        : "+f"(d0), "+f"(d1), "+f"(d2), "+f"(d3)
        : "r"(a0), "r"(a1), "r"(a2), "r"(a3), "r"(b0), "r"(b1));
}
// fp16-acc HMMA, accumulate into d
__device__ __forceinline__ void mma_h_acc(unsigned& d0, unsigned& d1,
                                          unsigned a0, unsigned a1, unsigned a2, unsigned a3,
                                          unsigned b0, unsigned b1) {
    asm volatile(
        "mma.sync.aligned.m16n8k16.row.col.f16.f16.f16.f16 "
        "{%0,%1}, {%2,%3,%4,%5}, {%6,%7}, {%0,%1};"
        : "+r"(d0), "+r"(d1)
        : "r"(a0), "r"(a1), "r"(a2), "r"(a3), "r"(b0), "r"(b1));
}
// fp16-acc HMMA, C = 0
__device__ __forceinline__ void mma_h_zero(unsigned& d0, unsigned& d1,
                                           unsigned a0, unsigned a1, unsigned a2, unsigned a3,
                                           unsigned b0, unsigned b1) {
    asm volatile(
        "mma.sync.aligned.m16n8k16.row.col.f16.f16.f16.f16 "
        "{%0,%1}, {%2,%3,%4,%5}, {%6,%7}, {%8,%8};"
        : "=r"(d0), "=r"(d1)
        : "r"(a0), "r"(a1), "r"(a2), "r"(a3), "r"(b0), "r"(b1), "r"(0u));
}
__device__ __forceinline__ void bar_group(int id) {
    asm volatile("bar.sync %0, 128;" :: "r"(id) : "memory");
}

// One CTA: 32 batch rows x one LSTM run. HMMA fp16 recurrent GEMM with fp16
// accumulators for intermediate steps (gates emerge as half2 (i,f)/(g,o) pairs
// -> pure-half2 epilogue). Final step uses fp32-acc MMA + fp32 epilogue.
// i/f/o weights pre-scaled 0.5 so sigmoid(x)=0.5*tanh(acc)+0.5. rg halves
// sync on named barriers.
__global__ __launch_bounds__(256, 2) void lstm_mma_kernel(
    const float* __restrict__ x0, const float* __restrict__ x1, const float* __restrict__ x2,
    const float* __restrict__ q00_wih, const float* __restrict__ q00_whh, const float* __restrict__ q00_b,
    const float* __restrict__ q01_wih, const float* __restrict__ q01_whh, const float* __restrict__ q01_b,
    const float* __restrict__ i00_wih, const float* __restrict__ i00_whh, const float* __restrict__ i00_b,
    const float* __restrict__ i01_wih, const float* __restrict__ i01_whh, const float* __restrict__ i01_b,
    const float* __restrict__ i02_wih, const float* __restrict__ i02_whh, const float* __restrict__ i02_b)
{
    extern __shared__ char smem[];
    const unsigned sb = smem_u32(smem);

    const float* x; const float* wih; const float* whh; const float* bias;
    float* hout; int coloff;
    switch (blockIdx.y) {
        case 0:  x = x0; wih = q00_wih; whh = q00_whh; bias = q00_b; hout = g_hq; coloff = 0;   break;
        case 1:  x = x1; wih = q01_wih; whh = q01_whh; bias = q01_b; hout = g_hq; coloff = 64;  break;
        case 2:  x = x2; wih = q01_wih; whh = q01_whh; bias = q01_b; hout = g_hq; coloff = 128; break;
        case 3:  x = x0; wih = i00_wih; whh = i00_whh; bias = i00_b; hout = g_hi; coloff = 0;   break;
        case 4:  x = x1; wih = i01_wih; whh = i01_whh; bias = i01_b; hout = g_hi; coloff = 64;  break;
        default: x = x2; wih = i02_wih; whh = i02_whh; bias = i02_b; hout = g_hi; coloff = 128; break;
    }

    const int tid  = threadIdx.x;
    const int wid  = tid >> 5;
    const int lane = tid & 31;
    const int rg   = wid & 1;        // 16-row group
    const int gq   = wid >> 1;       // 64-gate quarter (0..3)
    const int g    = lane >> 2;
    const int tl   = lane & 3;
    const int r0g  = blockIdx.x * MROWS;

    // ---- stage whh fp16, permuted, 0.5-scaled for i/f/o (tg != 2) ----
    __half* ws = (__half*)(smem + OFF_WS);
    for (int idx = tid; idx < 256 * 64; idx += 256) {
        int go = idx >> 6, k = idx & 63;
        int tg = go >> 6, u = go & 63;
        int p  = (u & 3) * 2 + (tg & 1) + 8 * (tg >> 1) + 16 * (u >> 2);
        float sc = (tg == 2) ? 1.0f : 0.5f;
        ws[p * 72 + k] = __float2half(whh[idx] * sc);
    }
    // permuted {wih, b} table (final fp32 step only), same 0.5 scale for i/f/o
    {
        int go = tid;
        int tg = go >> 6, u = go & 63;
        int p  = (u & 3) * 2 + (tg & 1) + 8 * (tg >> 1) + 16 * (u >> 2);
        float sc = (tg == 2) ? 1.0f : 0.5f;
        ((float2*)(smem + OFF_WBS))[p] = make_float2(wih[go] * sc, bias[go] * sc);
    }
    // x tile [32][33]
    float* xs = (float*)(smem + OFF_XS);
    for (int idx = tid; idx < MROWS * TT; idx += 256) {
        int r = idx >> 5, tt = idx & 31;
        xs[r * 33 + tt] = x[(size_t)(r0g + r) * TT + tt];
    }
    __syncthreads();

    // per-lane ldmatrix addresses
    const int rowA  = rg * 16 + (lane & 7) + 8 * ((lane >> 3) & 1);
    const unsigned aoff = (unsigned)(rowA * 144 + (lane >> 4) * 16);
    const int rowBb = gq * 64 + (lane & 7) + 8 * (lane >> 4);
    const unsigned boff = (unsigned)(rowBb * 144 + ((lane >> 3) & 1) * 16);

    const int r0 = rg * 16 + g;       // this thread's rows
    const int r1 = r0 + 8;

    // hoist B fragments for kc = 0,1 into registers (static weights)
    unsigned bw[8][4];
    #pragma unroll
    for (int kc = 0; kc < 2; ++kc)
        #pragma unroll
        for (int np = 0; np < 4; ++np)
            ldsm_x4(sb + OFF_WS + boff + (unsigned)(np * 16 * 144 + kc * 32),
                    bw[kc * 4 + np][0], bw[kc * 4 + np][1],
                    bw[kc * 4 + np][2], bw[kc * 4 + np][3]);

    // hoisted half2 fold constants: per q, unit u = 16gq + 4q + tl
    __half2 w_if2[4], b_if2[4], w_go2[4], b_go2[4];
    #pragma unroll
    for (int q = 0; q < 4; ++q) {
        int u = 16 * gq + 4 * q + tl;
        w_if2[q] = __floats2half2_rn(0.5f * wih[u], 0.5f * wih[64 + u]);
        b_if2[q] = __floats2half2_rn(0.5f * bias[u], 0.5f * bias[64 + u]);
        w_go2[q] = __floats2half2_rn(wih[128 + u], 0.5f * wih[192 + u]);
        b_go2[q] = __floats2half2_rn(bias[128 + u], 0.5f * bias[192 + u]);
    }

    __half2 c2[4];
    #pragma unroll
    for (int i = 0; i < 4; ++i) c2[i] = __floats2half2_rn(0.f, 0.f);

    const __half2 h05   = __floats2half2_rn(0.5f, 0.5f);
    const __half2 m1_05 = __floats2half2_rn(1.0f, 0.5f);
    const __half2 a0_05 = __floats2half2_rn(0.0f, 0.5f);
    const int barid = 1 + rg;

    unsigned aif[4][2], ago[4][2];
    #pragma unroll
    for (int np = 0; np < 4; ++np) {
        aif[np][0] = aif[np][1] = 0u;
        ago[np][0] = ago[np][1] = 0u;
    }

    #pragma unroll 1
    for (int t = 0; t < TT - 1; ++t) {
        if (t > 0) {
            const unsigned rbase = sb + OFF_HS + ((unsigned)((t + 1) & 1)) * HS_BUF;
            #pragma unroll
            for (int kc = 0; kc < 4; ++kc) {
                unsigned ah0, ah1, ah2, ah3;
                ldsm_x4(rbase + aoff + kc * 32, ah0, ah1, ah2, ah3);
                #pragma unroll
                for (int np = 0; np < 4; ++np) {
                    unsigned b0, b1, b2, b3;
                    if (kc < 2) {
                        b0 = bw[kc * 4 + np][0]; b1 = bw[kc * 4 + np][1];
                        b2 = bw[kc * 4 + np][2]; b3 = bw[kc * 4 + np][3];
                    } else {
                        ldsm_x4(sb + OFF_WS + boff + (unsigned)(np * 16 * 144 + kc * 32),
                                b0, b1, b2, b3);
                    }
                    if (kc == 0) {
                        mma_h_zero(aif[np][0], aif[np][1], ah0, ah1, ah2, ah3, b0, b1);
                        mma_h_zero(ago[np][0], ago[np][1], ah0, ah1, ah2, ah3, b2, b3);
                    } else {
                        mma_h_acc(aif[np][0], aif[np][1], ah0, ah1, ah2, ah3, b0, b1);
                        mma_h_acc(ago[np][0], ago[np][1], ah0, ah1, ah2, ah3, b2, b3);
                    }
                }
            }
        }

        // pure-half2 epilogue
        __half* hw = (__half*)(smem + OFF_HS + (t & 1) * HS_BUF);
        __half2 xh0 = __half2half2(__float2half(xs[r0 * 33 + t]));
        __half2 xh1 = __half2half2(__float2half(xs[r1 * 33 + t]));
        #pragma unroll
        for (int q = 0; q < 4; ++q) {
            int u = 16 * gq + 4 * q + tl;
            __half2 if0 = __hadd2(*(__half2*)&aif[q][0], __hfma2(w_if2[q], xh0, b_if2[q]));
            __half2 if1 = __hadd2(*(__half2*)&aif[q][1], __hfma2(w_if2[q], xh1, b_if2[q]));
            __half2 go0 = __hadd2(*(__half2*)&ago[q][0], __hfma2(w_go2[q], xh0, b_go2[q]));
            __half2 go1 = __hadd2(*(__half2*)&ago[q][1], __hfma2(w_go2[q], xh1, b_go2[q]));

            __half2 sif0 = __hfma2(tanh2_ap(if0), h05, h05);
            __half2 sif1 = __hfma2(tanh2_ap(if1), h05, h05);
            __half2 gso0 = __hfma2(tanh2_ap(go0), m1_05, a0_05);
            __half2 gso1 = __hfma2(tanh2_ap(go1), m1_05, a0_05);

            __half2 si2 = __lows2half2(sif0, sif1);
            __half2 sf2 = __highs2half2(sif0, sif1);
            __half2 tg2 = __lows2half2(gso0, gso1);
            __half2 so2 = __highs2half2(gso0, gso1);
            c2[q] = __hfma2(sf2, c2[q], __hmul2(si2, tg2));
            __half2 h2v = __hmul2(so2, tanh2_ap(c2[q]));
            hw[r0 * 72 + u] = __low2half(h2v);
            hw[r1 * 72 + u] = __high2half(h2v);
        }
        bar_group(barid);
    }

    // ---- final step (t = TT-1): fp32-acc MMA + fp32 epilogue ----
    {
        const int t = TT - 1;
        float acc[32];
        #pragma unroll
        for (int i = 0; i < 32; ++i) acc[i] = 0.f;
        const unsigned rbase = sb + OFF_HS + ((unsigned)((t + 1) & 1)) * HS_BUF;
        #pragma unroll
        for (int kc = 0; kc < 4; ++kc) {
            unsigned ah0, ah1, ah2, ah3;
            ldsm_x4(rbase + aoff + kc * 32, ah0, ah1, ah2, ah3);
            #pragma unroll
            for (int np = 0; np < 4; ++np) {
                unsigned b0, b1, b2, b3;
                if (kc < 2) {
                    b0 = bw[kc * 4 + np][0]; b1 = bw[kc * 4 + np][1];
                    b2 = bw[kc * 4 + np][2]; b3 = bw[kc * 4 + np][3];
                } else {
                    ldsm_x4(sb + OFF_WS + boff + (unsigned)(np * 16 * 144 + kc * 32),
                            b0, b1, b2, b3);
                }
                float* e = acc + np * 8;
                mma16816(e[0], e[1], e[2], e[3], ah0, ah1, ah2, ah3, b0, b1);
                mma16816(e[4], e[5], e[6], e[7], ah0, ah1, ah2, ah3, b2, b3);
            }
        }
        const float4* wbs4 = (const float4*)(smem + OFF_WBS);
        float xv0 = xs[r0 * 33 + t];
        float xv1 = xs[r1 * 33 + t];
        #pragma unroll
        for (int q = 0; q < 4; ++q) {
            int pq = 16 * (gq * 4 + q) + 2 * tl;
            float4 wif = wbs4[pq >> 1];
            float4 wgo = wbs4[(pq >> 1) + 4];
            int u = 16 * gq + 4 * q + tl;
            float2 cf = __half22float2(c2[q]);
            #pragma unroll
            for (int rowj = 0; rowj < 2; ++rowj) {
                float xv = rowj ? xv1 : xv0;
                float iv = acc[8 * q + rowj * 2 + 0] + fmaf(wif.x, xv, wif.y);
                float fv = acc[8 * q + rowj * 2 + 1] + fmaf(wif.z, xv, wif.w);
                float gv = acc[8 * q + 4 + rowj * 2 + 0] + fmaf(wgo.x, xv, wgo.y);
                float ov = acc[8 * q + 4 + rowj * 2 + 1] + fmaf(wgo.z, xv, wgo.w);
                float si = fmaf(0.5f, tanh_ap(iv), 0.5f);
                float sf = fmaf(0.5f, tanh_ap(fv), 0.5f);
                float so = fmaf(0.5f, tanh_ap(ov), 0.5f);
                float cold = rowj ? cf.y : cf.x;
                float cc = sf * cold + si * tanh_ap(gv);
                float h = so * tanh_ap(cc);
                int row = rowj ? r1 : r0;
                hout[(size_t)(r0g + row) * 192 + coloff + u] = h;
            }
        }
    }
}

// Head v2: grid (64, 2): 64 rows x one branch per CTA. GEMM1 on HMMA fp16
// (fp32 acc): A = concat vector [64][256] fp16, B = w1 [64][256] fp16 (natural
// layout, no transpose staging). Warp w: mt = w&3 (16-row tile), nh = w>>2
// (32-col half). GEMV2 (64x6) + softmax scalar fp32.
__global__ __launch_bounds__(256) void head_kernel(
    const float* __restrict__ s2,
    const float* __restrict__ q03_w, const float* __restrict__ q03_b,
    const float* __restrict__ q1_w,  const float* __restrict__ q1_b,
    const float* __restrict__ q2_w,  const float* __restrict__ q2_b,
    const float* __restrict__ i03_w, const float* __restrict__ i03_b,
    const float* __restrict__ i1_w,  const float* __restrict__ i1_b,
    const float* __restrict__ i2_w,  const float* __restrict__ i2_b,
    float* __restrict__ out)
{
    extern __shared__ char smh[];
    const unsigned sbh = smem_u32(smh);
    __half* Ah = (__half*)(smh + H_AH);       // [64][264] halves
    __half* Bh = (__half*)(smh + H_BH);       // [64][264]
    float* qb  = (float*)(smh + H_QB);        // [64][66]
    float* ib  = (float*)(smh + H_IB);        // [64][8]

    const int tid  = threadIdx.x;
    const int wid  = tid >> 5;
    const int lane = tid & 31;
    const int row0 = blockIdx.x * 64;
    const int br   = blockIdx.y;

    const float* gh  = br ? g_hi  : g_hq;
    const float* w03 = br ? i03_w : q03_w;
    const float* b03 = br ? i03_b : q03_b;
    const float* w1  = br ? i1_w  : q1_w;
    const float* b1  = br ? i1_b  : q1_b;
    const float* w2  = br ? i2_w  : q2_w;
    const float* b2  = br ? i2_b  : q2_b;

    // stage A cols [0:192) from lstm outputs (float4 vectorized)
    for (int idx = tid; idx < 64 * 48; idx += 256) {
        int r = idx / 48, k4 = idx - r * 48;
        float4 v = *(const float4*)&gh[(size_t)(row0 + r) * 192 + k4 * 4];
        __half2* d = (__half2*)&Ah[r * 264 + k4 * 4];
        d[0] = __floats2half2_rn(v.x, v.y);
        d[1] = __floats2half2_rn(v.z, v.w);
    }
    // stage A cols [192:256): relu(s2 @ w03 + b03)
    for (int idx = tid; idx < 64 * 64; idx += 256) {
        int r = idx >> 6, u = idx & 63;
        const float* s = &s2[(row0 + r) * 3];
        float a = b03[u] + s[0] * w03[u * 3] + s[1] * w03[u * 3 + 1] + s[2] * w03[u * 3 + 2];
        Ah[r * 264 + 192 + u] = __float2half(fmaxf(a, 0.f));
    }
    // stage B = w1 [64 u][256 k] (float4 vectorized)
    for (int idx = tid; idx < 64 * 64; idx += 256) {
        int u = idx >> 6, k4 = idx & 63;
        float4 v = *(const float4*)&w1[u * 256 + k4 * 4];
        __half2* d = (__half2*)&Bh[u * 264 + k4 * 4];
        d[0] = __floats2half2_rn(v.x, v.y);
        d[1] = __floats2half2_rn(v.z, v.w);
    }
    __syncthreads();

    // GEMM1: warp (mt, nh): rows mt*16..+15, cols nh*32..+31
    const int mt = wid & 3;
    const int nh = wid >> 2;
    const int g  = lane >> 2;
    const int tl = lane & 3;
    const unsigned abase = sbh + H_AH +
        (unsigned)((mt * 16 + (lane & 7) + 8 * ((lane >> 3) & 1)) * 528 + (lane >> 4) * 16);
    const unsigned bbase0 = sbh + H_BH +
        (unsigned)((nh * 32 + (lane & 7) + 8 * (lane >> 4)) * 528 + ((lane >> 3) & 1) * 16);
    const unsigned bbase1 = bbase0 + 16 * 528;

    float acc[16];
    #pragma unroll
    for (int i = 0; i < 16; ++i) acc[i] = 0.f;

    #pragma unroll
    for (int kc = 0; kc < 16; ++kc) {
        unsigned a0, a1, a2, a3, b0, b1, b2, b3;
        ldsm_x4(abase + kc * 32, a0, a1, a2, a3);
        ldsm_x4(bbase0 + kc * 32, b0, b1, b2, b3);
        mma16816(acc[0], acc[1], acc[2], acc[3], a0, a1, a2, a3, b0, b1);
        mma16816(acc[4], acc[5], acc[6], acc[7], a0, a1, a2, a3, b2, b3);
        ldsm_x4(bbase1 + kc * 32, b0, b1, b2, b3);
        mma16816(acc[8], acc[9], acc[10], acc[11], a0, a1, a2, a3, b0, b1);
        mma16816(acc[12], acc[13], acc[14], acc[15], a0, a1, a2, a3, b2, b3);
    }

    // relu + bias -> qb
    const int r0h = mt * 16 + g;
    const int r1h = r0h + 8;
    #pragma unroll
    for (int nt = 0; nt < 4; ++nt) {
        int col = nh * 32 + nt * 8 + tl * 2;
        float bb0 = b1[col], bb1 = b1[col + 1];
        qb[r0h * 66 + col]     = fmaxf(acc[nt * 4 + 0] + bb0, 0.f);
        qb[r0h * 66 + col + 1] = fmaxf(acc[nt * 4 + 1] + bb1, 0.f);
        qb[r1h * 66 + col]     = fmaxf(acc[nt * 4 + 2] + bb0, 0.f);
        qb[r1h * 66 + col + 1] = fmaxf(acc[nt * 4 + 3] + bb1, 0.f);
    }
    __syncthreads();

    // GEMV2: 64 rows x 6 outputs
    for (int it = tid; it < 64 * AA; it += 256) {
        int r = it / AA;
        int a = it - r * AA;
        float acc2 = b2[a];
        #pragma unroll 8
        for (int k = 0; k < 64; ++k)
            acc2 = fmaf(w2[a * 64 + k], qb[r * 66 + k], acc2);
        if (br == 0) out[(row0 + r) * AA + a] = acc2;        // q (no relu)
        else         ib[r * 8 + a] = fmaxf(acc2, 0.f);       // i vec
    }
    if (br == 1) {
        __syncthreads();
        if (tid < 64) {
            int r = tid;
            float m = ib[r * 8];
            #pragma unroll
            for (int j = 1; j < AA; ++j) m = fmaxf(m, ib[r * 8 + j]);
            float s = 0.f;
            #pragma unroll
            for (int j = 0; j < AA; ++j) s += __expf(ib[r * 8 + j] - m);
            float lse = m + __logf(s);
            #pragma unroll
            for (int j = 0; j < AA; ++j) {
                float iv = ib[r * 8 + j];
                out[BB * AA + (row0 + r) * AA + j]     = iv - lse;
                out[2 * BB * AA + (row0 + r) * AA + j] = iv;
            }
        }
    }
}

extern "C" void kernel_launch(void* const* d_in, const int* in_sizes, int n_in,
                              void* d_out, int out_size)
{
    const float* x0 = (const float*)d_in[0];
    const float* x1 = (const float*)d_in[1];
    const float* x2 = (const float*)d_in[2];
    const float* s2 = (const float*)d_in[3];
    const float* q00_wih = (const float*)d_in[4];
    const float* q00_whh = (const float*)d_in[5];
    const float* q00_b   = (const float*)d_in[6];
    const float* q01_wih = (const float*)d_in[7];
    const float* q01_whh = (const float*)d_in[8];
    const float* q01_b   = (const float*)d_in[9];
    const float* i00_wih = (const float*)d_in[10];
    const float* i00_whh = (const float*)d_in[11];
    const float* i00_b   = (const float*)d_in[12];
    const float* i01_wih = (const float*)d_in[13];
    const float* i01_whh = (const float*)d_in[14];
    const float* i01_b   = (const float*)d_in[15];
    const float* i02_wih = (const float*)d_in[16];
    const float* i02_whh = (const float*)d_in[17];
    const float* i02_b   = (const float*)d_in[18];
    const float* q03_w = (const float*)d_in[19];
    const float* q03_b = (const float*)d_in[20];
    const float* q1_w  = (const float*)d_in[21];
    const float* q1_b  = (const float*)d_in[22];
    const float* q2_w  = (const float*)d_in[23];
    const float* q2_b  = (const float*)d_in[24];
    const float* i03_w = (const float*)d_in[25];
    const float* i03_b = (const float*)d_in[26];
    const float* i1_w  = (const float*)d_in[27];
    const float* i1_b  = (const float*)d_in[28];
    const float* i2_w  = (const float*)d_in[29];
    const float* i2_b  = (const float*)d_in[30];
    float* out = (float*)d_out;

    cudaFuncSetAttribute(lstm_mma_kernel, cudaFuncAttributeMaxDynamicSharedMemorySize, LSTM_SMEM_BYTES);
    cudaFuncSetAttribute(head_kernel, cudaFuncAttributeMaxDynamicSharedMemorySize, HEAD_SMEM_BYTES);

    dim3 grid(BB / MROWS, 6);   // 128 batch tiles x 6 LSTM runs = 768 CTAs, 2/SM
    lstm_mma_kernel<<<grid, 256, LSTM_SMEM_BYTES>>>(
        x0, x1, x2,
        q00_wih, q00_whh, q00_b,
        q01_wih, q01_whh, q01_b,
        i00_wih, i00_whh, i00_b,
        i01_wih, i01_whh, i01_b,
        i02_wih, i02_whh, i02_b);

    head_kernel<<<dim3(BB / 64, 2), 256, HEAD_SMEM_BYTES>>>(
        s2,
        q03_w, q03_b, q1_w, q1_b, q2_w, q2_b,
        i03_w, i03_b, i1_w, i1_b, i2_w, i2_b,
        out);
}

// round 13
// speedup vs baseline: 7.0158x; 1.0262x over previous
#include <cuda_runtime.h>
#include <cuda_fp16.h>

// Problem constants
#define HH    64
#define TT    32
#define BB    4096
#define AA    6
#define MROWS 32        // batch rows per lstm CTA

// lstm smem layout (bytes). Rows padded to 144B (72 halves) for conflict-free ldmatrix.
#define OFF_WS  0                    // Ws [256][72] half : weights fp16 (i/f/o pre-scaled 0.5)
#define OFF_HS  36864                // hs double buffer: 2 x [32][72] half
#define HS_BUF  4608                 // bytes per h buffer
#define OFF_WBS 46080                // float2[256] permuted {wih, b} (final step only)
#define OFF_XS  48128                // float [32][33]
#define LSTM_SMEM_BYTES (OFF_XS + 32 * 33 * 4)   // 52352

// head kernel v3 (HMMA, 32 rows/CTA, 3 CTAs/SM): grid (128, 2) = 256 CTAs.
// A = concat [32][264] fp16, B = w1 [64][264] fp16.
#define H_AH 0                       // A fp16 [32][264]
#define H_BH 16896                   // B fp16 [64][264]
#define H_QB 50688                   // qb fp32 [32][66]
#define H_IB 59136                   // ib fp32 [32][8]
#define HEAD_SMEM_BYTES (H_IB + 1536)

// scratch: final hidden states fp16, [B][192] (3 LSTM outputs per branch)
__device__ __half g_hq[BB * 192];
__device__ __half g_hi[BB * 192];

__device__ __forceinline__ float tanh_ap(float x) {
    float y;
    asm("tanh.approx.f32 %0, %1;" : "=f"(y) : "f"(x));
    return y;
}
__device__ __forceinline__ __half2 tanh2_ap(__half2 x) {
    __half2 y;
    asm("tanh.approx.f16x2 %0, %1;" : "=r"(*(unsigned*)&y) : "r"(*(unsigned*)&x));
    return y;
}

__device__ __forceinline__ unsigned smem_u32(const void* p) {
    unsigned a;
    asm("{ .reg .u64 t; cvta.to.shared.u64 t, %1; cvt.u32.u64 %0, t; }" : "=r"(a) : "l"(p));
    return a;
}
__device__ __forceinline__ void ldsm_x4(unsigned addr, unsigned& r0, unsigned& r1,
                                        unsigned& r2, unsigned& r3) {
    asm volatile("ldmatrix.sync.aligned.m8n8.x4.shared.b16 {%0,%1,%2,%3}, [%4];"
                 : "=r"(r0), "=r"(r1), "=r"(r2), "=r"(r3) : "r"(addr));
}
// fp32-acc HMMA
__device__ __forceinline__ void mma16816(float& d0, float& d1, float& d2, float& d3,
                                         unsigned a0, unsigned a1, unsigned a2, unsigned a3,
                                         unsigned b0, unsigned b1) {
    asm volatile(
        "mma.sync.aligned.m16n8k16.row.col.f32.f16.f16.f32 "
        "{%0,%1,%2,%3}, {%4,%5,%6,%7}, {%8,%9}, {%0,%1,%2,%3};"
        : "+f"(d0), "+f"(d1), "+f"(d2), "+f"(d3)
        : "r"(a0), "r"(a1), "r"(a2), "r"(a3), "r"(b0), "r"(b1));
}
// fp16-acc HMMA, accumulate into d
__device__ __forceinline__ void mma_h_acc(unsigned& d0, unsigned& d1,
                                          unsigned a0, unsigned a1, unsigned a2, unsigned a3,
                                          unsigned b0, unsigned b1) {
    asm volatile(
        "mma.sync.aligned.m16n8k16.row.col.f16.f16.f16.f16 "
        "{%0,%1}, {%2,%3,%4,%5}, {%6,%7}, {%0,%1};"
        : "+r"(d0), "+r"(d1)
        : "r"(a0), "r"(a1), "r"(a2), "r"(a3), "r"(b0), "r"(b1));
}
// fp16-acc HMMA, C = 0
__device__ __forceinline__ void mma_h_zero(unsigned& d0, unsigned& d1,
                                           unsigned a0, unsigned a1, unsigned a2, unsigned a3,
                                           unsigned b0, unsigned b1) {
    asm volatile(
        "mma.sync.aligned.m16n8k16.row.col.f16.f16.f16.f16 "
        "{%0,%1}, {%2,%3,%4,%5}, {%6,%7}, {%8,%8};"
        : "=r"(d0), "=r"(d1)
        : "r"(a0), "r"(a1), "r"(a2), "r"(a3), "r"(b0), "r"(b1), "r"(0u));
}
__device__ __forceinline__ void bar_group(int id) {
    asm volatile("bar.sync %0, 128;" :: "r"(id) : "memory");
}

// One CTA: 32 batch rows x one LSTM run. HMMA fp16 recurrent GEMM with fp16
// accumulators for intermediate steps; final step fp32-acc MMA + fp32 epilogue,
// storing h as fp16 to global (the head quantizes to fp16 anyway).
__global__ __launch_bounds__(256, 2) void lstm_mma_kernel(
    const float* __restrict__ x0, const float* __restrict__ x1, const float* __restrict__ x2,
    const float* __restrict__ q00_wih, const float* __restrict__ q00_whh, const float* __restrict__ q00_b,
    const float* __restrict__ q01_wih, const float* __restrict__ q01_whh, const float* __restrict__ q01_b,
    const float* __restrict__ i00_wih, const float* __restrict__ i00_whh, const float* __restrict__ i00_b,
    const float* __restrict__ i01_wih, const float* __restrict__ i01_whh, const float* __restrict__ i01_b,
    const float* __restrict__ i02_wih, const float* __restrict__ i02_whh, const float* __restrict__ i02_b)
{
    extern __shared__ char smem[];
    const unsigned sb = smem_u32(smem);

    const float* x; const float* wih; const float* whh; const float* bias;
    __half* hout; int coloff;
    switch (blockIdx.y) {
        case 0:  x = x0; wih = q00_wih; whh = q00_whh; bias = q00_b; hout = g_hq; coloff = 0;   break;
        case 1:  x = x1; wih = q01_wih; whh = q01_whh; bias = q01_b; hout = g_hq; coloff = 64;  break;
        case 2:  x = x2; wih = q01_wih; whh = q01_whh; bias = q01_b; hout = g_hq; coloff = 128; break;
        case 3:  x = x0; wih = i00_wih; whh = i00_whh; bias = i00_b; hout = g_hi; coloff = 0;   break;
        case 4:  x = x1; wih = i01_wih; whh = i01_whh; bias = i01_b; hout = g_hi; coloff = 64;  break;
        default: x = x2; wih = i02_wih; whh = i02_whh; bias = i02_b; hout = g_hi; coloff = 128; break;
    }

    const int tid  = threadIdx.x;
    const int wid  = tid >> 5;
    const int lane = tid & 31;
    const int rg   = wid & 1;        // 16-row group
    const int gq   = wid >> 1;       // 64-gate quarter (0..3)
    const int g    = lane >> 2;
    const int tl   = lane & 3;
    const int r0g  = blockIdx.x * MROWS;

    // ---- stage whh fp16, permuted, 0.5-scaled for i/f/o (tg != 2) ----
    __half* ws = (__half*)(smem + OFF_WS);
    for (int idx = tid; idx < 256 * 64; idx += 256) {
        int go = idx >> 6, k = idx & 63;
        int tg = go >> 6, u = go & 63;
        int p  = (u & 3) * 2 + (tg & 1) + 8 * (tg >> 1) + 16 * (u >> 2);
        float sc = (tg == 2) ? 1.0f : 0.5f;
        ws[p * 72 + k] = __float2half(whh[idx] * sc);
    }
    // permuted {wih, b} table (final fp32 step only), same 0.5 scale for i/f/o
    {
        int go = tid;
        int tg = go >> 6, u = go & 63;
        int p  = (u & 3) * 2 + (tg & 1) + 8 * (tg >> 1) + 16 * (u >> 2);
        float sc = (tg == 2) ? 1.0f : 0.5f;
        ((float2*)(smem + OFF_WBS))[p] = make_float2(wih[go] * sc, bias[go] * sc);
    }
    // x tile [32][33]
    float* xs = (float*)(smem + OFF_XS);
    for (int idx = tid; idx < MROWS * TT; idx += 256) {
        int r = idx >> 5, tt = idx & 31;
        xs[r * 33 + tt] = x[(size_t)(r0g + r) * TT + tt];
    }
    __syncthreads();

    // per-lane ldmatrix addresses
    const int rowA  = rg * 16 + (lane & 7) + 8 * ((lane >> 3) & 1);
    const unsigned aoff = (unsigned)(rowA * 144 + (lane >> 4) * 16);
    const int rowBb = gq * 64 + (lane & 7) + 8 * (lane >> 4);
    const unsigned boff = (unsigned)(rowBb * 144 + ((lane >> 3) & 1) * 16);

    const int r0 = rg * 16 + g;       // this thread's rows
    const int r1 = r0 + 8;

    // hoist B fragments for kc = 0,1 into registers (static weights)
    unsigned bw[8][4];
    #pragma unroll
    for (int kc = 0; kc < 2; ++kc)
        #pragma unroll
        for (int np = 0; np < 4; ++np)
            ldsm_x4(sb + OFF_WS + boff + (unsigned)(np * 16 * 144 + kc * 32),
                    bw[kc * 4 + np][0], bw[kc * 4 + np][1],
                    bw[kc * 4 + np][2], bw[kc * 4 + np][3]);

    // hoisted half2 fold constants: per q, unit u = 16gq + 4q + tl
    __half2 w_if2[4], b_if2[4], w_go2[4], b_go2[4];
    #pragma unroll
    for (int q = 0; q < 4; ++q) {
        int u = 16 * gq + 4 * q + tl;
        w_if2[q] = __floats2half2_rn(0.5f * wih[u], 0.5f * wih[64 + u]);
        b_if2[q] = __floats2half2_rn(0.5f * bias[u], 0.5f * bias[64 + u]);
        w_go2[q] = __floats2half2_rn(wih[128 + u], 0.5f * wih[192 + u]);
        b_go2[q] = __floats2half2_rn(bias[128 + u], 0.5f * bias[192 + u]);
    }

    __half2 c2[4];
    #pragma unroll
    for (int i = 0; i < 4; ++i) c2[i] = __floats2half2_rn(0.f, 0.f);

    const __half2 h05   = __floats2half2_rn(0.5f, 0.5f);
    const __half2 m1_05 = __floats2half2_rn(1.0f, 0.5f);
    const __half2 a0_05 = __floats2half2_rn(0.0f, 0.5f);
    const int barid = 1 + rg;

    unsigned aif[4][2], ago[4][2];
    #pragma unroll
    for (int np = 0; np < 4; ++np) {
        aif[np][0] = aif[np][1] = 0u;
        ago[np][0] = ago[np][1] = 0u;
    }

    #pragma unroll 1
    for (int t = 0; t < TT - 1; ++t) {
        if (t > 0) {
            const unsigned rbase = sb + OFF_HS + ((unsigned)((t + 1) & 1)) * HS_BUF;
            #pragma unroll
            for (int kc = 0; kc < 4; ++kc) {
                unsigned ah0, ah1, ah2, ah3;
                ldsm_x4(rbase + aoff + kc * 32, ah0, ah1, ah2, ah3);
                #pragma unroll
                for (int np = 0; np < 4; ++np) {
                    unsigned b0, b1, b2, b3;
                    if (kc < 2) {
                        b0 = bw[kc * 4 + np][0]; b1 = bw[kc * 4 + np][1];
                        b2 = bw[kc * 4 + np][2]; b3 = bw[kc * 4 + np][3];
                    } else {
                        ldsm_x4(sb + OFF_WS + boff + (unsigned)(np * 16 * 144 + kc * 32),
                                b0, b1, b2, b3);
                    }
                    if (kc == 0) {
                        mma_h_zero(aif[np][0], aif[np][1], ah0, ah1, ah2, ah3, b0, b1);
                        mma_h_zero(ago[np][0], ago[np][1], ah0, ah1, ah2, ah3, b2, b3);
                    } else {
                        mma_h_acc(aif[np][0], aif[np][1], ah0, ah1, ah2, ah3, b0, b1);
                        mma_h_acc(ago[np][0], ago[np][1], ah0, ah1, ah2, ah3, b2, b3);
                    }
                }
            }
        }

        // pure-half2 epilogue
        __half* hw = (__half*)(smem + OFF_HS + (t & 1) * HS_BUF);
        __half2 xh0 = __half2half2(__float2half(xs[r0 * 33 + t]));
        __half2 xh1 = __half2half2(__float2half(xs[r1 * 33 + t]));
        #pragma unroll
        for (int q = 0; q < 4; ++q) {
            int u = 16 * gq + 4 * q + tl;
            __half2 if0 = __hadd2(*(__half2*)&aif[q][0], __hfma2(w_if2[q], xh0, b_if2[q]));
            __half2 if1 = __hadd2(*(__half2*)&aif[q][1], __hfma2(w_if2[q], xh1, b_if2[q]));
            __half2 go0 = __hadd2(*(__half2*)&ago[q][0], __hfma2(w_go2[q], xh0, b_go2[q]));
            __half2 go1 = __hadd2(*(__half2*)&ago[q][1], __hfma2(w_go2[q], xh1, b_go2[q]));

            __half2 sif0 = __hfma2(tanh2_ap(if0), h05, h05);
            __half2 sif1 = __hfma2(tanh2_ap(if1), h05, h05);
            __half2 gso0 = __hfma2(tanh2_ap(go0), m1_05, a0_05);
            __half2 gso1 = __hfma2(tanh2_ap(go1), m1_05, a0_05);

            __half2 si2 = __lows2half2(sif0, sif1);
            __half2 sf2 = __highs2half2(sif0, sif1);
            __half2 tg2 = __lows2half2(gso0, gso1);
            __half2 so2 = __highs2half2(gso0, gso1);
            c2[q] = __hfma2(sf2, c2[q], __hmul2(si2, tg2));
            __half2 h2v = __hmul2(so2, tanh2_ap(c2[q]));
            hw[r0 * 72 + u] = __low2half(h2v);
            hw[r1 * 72 + u] = __high2half(h2v);
        }
        bar_group(barid);
    }

    // ---- final step (t = TT-1): fp32-acc MMA + fp32 epilogue, fp16 store ----
    {
        const int t = TT - 1;
        float acc[32];
        #pragma unroll
        for (int i = 0; i < 32; ++i) acc[i] = 0.f;
        const unsigned rbase = sb + OFF_HS + ((unsigned)((t + 1) & 1)) * HS_BUF;
        #pragma unroll
        for (int kc = 0; kc < 4; ++kc) {
            unsigned ah0, ah1, ah2, ah3;
            ldsm_x4(rbase + aoff + kc * 32, ah0, ah1, ah2, ah3);
            #pragma unroll
            for (int np = 0; np < 4; ++np) {
                unsigned b0, b1, b2, b3;
                if (kc < 2) {
                    b0 = bw[kc * 4 + np][0]; b1 = bw[kc * 4 + np][1];
                    b2 = bw[kc * 4 + np][2]; b3 = bw[kc * 4 + np][3];
                } else {
                    ldsm_x4(sb + OFF_WS + boff + (unsigned)(np * 16 * 144 + kc * 32),
                            b0, b1, b2, b3);
                }
                float* e = acc + np * 8;
                mma16816(e[0], e[1], e[2], e[3], ah0, ah1, ah2, ah3, b0, b1);
                mma16816(e[4], e[5], e[6], e[7], ah0, ah1, ah2, ah3, b2, b3);
            }
        }
        const float4* wbs4 = (const float4*)(smem + OFF_WBS);
        float xv0 = xs[r0 * 33 + t];
        float xv1 = xs[r1 * 33 + t];
        #pragma unroll
        for (int q = 0; q < 4; ++q) {
            int pq = 16 * (gq * 4 + q) + 2 * tl;
            float4 wif = wbs4[pq >> 1];
            float4 wgo = wbs4[(pq >> 1) + 4];
            int u = 16 * gq + 4 * q + tl;
            float2 cf = __half22float2(c2[q]);
            #pragma unroll
            for (int rowj = 0; rowj < 2; ++rowj) {
                float xv = rowj ? xv1 : xv0;
                float iv = acc[8 * q + rowj * 2 + 0] + fmaf(wif.x, xv, wif.y);
                float fv = acc[8 * q + rowj * 2 + 1] + fmaf(wif.z, xv, wif.w);
                float gv = acc[8 * q + 4 + rowj * 2 + 0] + fmaf(wgo.x, xv, wgo.y);
                float ov = acc[8 * q + 4 + rowj * 2 + 1] + fmaf(wgo.z, xv, wgo.w);
                float si = fmaf(0.5f, tanh_ap(iv), 0.5f);
                float sf = fmaf(0.5f, tanh_ap(fv), 0.5f);
                float so = fmaf(0.5f, tanh_ap(ov), 0.5f);
                float cold = rowj ? cf.y : cf.x;
                float cc = sf * cold + si * tanh_ap(gv);
                float h = so * tanh_ap(cc);
                int row = rowj ? r1 : r0;
                hout[(size_t)(r0g + row) * 192 + coloff + u] = __float2half(h);
            }
        }
    }
}

// Head v3: grid (128, 2): 32 rows x one branch per CTA, ~60KB smem -> 3 CTAs/SM.
// A staged by uint4 copy from fp16 hidden states (no conversion). GEMM1 on
// HMMA fp16/fp32-acc; warp (mt, nq) = (16-row tile, 16-col quarter).
__global__ __launch_bounds__(256) void head_kernel(
    const float* __restrict__ s2,
    const float* __restrict__ q03_w, const float* __restrict__ q03_b,
    const float* __restrict__ q1_w,  const float* __restrict__ q1_b,
    const float* __restrict__ q2_w,  const float* __restrict__ q2_b,
    const float* __restrict__ i03_w, const float* __restrict__ i03_b,
    const float* __restrict__ i1_w,  const float* __restrict__ i1_b,
    const float* __restrict__ i2_w,  const float* __restrict__ i2_b,
    float* __restrict__ out)
{
    extern __shared__ char smh[];
    const unsigned sbh = smem_u32(smh);
    __half* Ah = (__half*)(smh + H_AH);       // [32][264] halves
    __half* Bh = (__half*)(smh + H_BH);       // [64][264]
    float* qb  = (float*)(smh + H_QB);        // [32][66]
    float* ib  = (float*)(smh + H_IB);        // [32][8]

    const int tid  = threadIdx.x;
    const int wid  = tid >> 5;
    const int lane = tid & 31;
    const int row0 = blockIdx.x * 32;
    const int br   = blockIdx.y;

    const __half* gh = br ? g_hi  : g_hq;
    const float* w03 = br ? i03_w : q03_w;
    const float* b03 = br ? i03_b : q03_b;
    const float* w1  = br ? i1_w  : q1_w;
    const float* b1  = br ? i1_b  : q1_b;
    const float* w2  = br ? i2_w  : q2_w;
    const float* b2  = br ? i2_b  : q2_b;

    // stage A cols [0:192): raw uint4 copy of fp16 hidden states (24 uint4/row)
    for (int idx = tid; idx < 32 * 24; idx += 256) {
        int r = idx / 24, c8 = idx - r * 24;
        uint4 v = *(const uint4*)&gh[(size_t)(row0 + r) * 192 + c8 * 8];
        *(uint4*)&Ah[r * 264 + c8 * 8] = v;
    }
    // stage A cols [192:256): relu(s2 @ w03 + b03)
    for (int idx = tid; idx < 32 * 64; idx += 256) {
        int r = idx >> 6, u = idx & 63;
        const float* s = &s2[(row0 + r) * 3];
        float a = b03[u] + s[0] * w03[u * 3] + s[1] * w03[u * 3 + 1] + s[2] * w03[u * 3 + 2];
        Ah[r * 264 + 192 + u] = __float2half(fmaxf(a, 0.f));
    }
    // stage B = w1 [64 u][256 k] (float4 vectorized, fp32 -> fp16)
    for (int idx = tid; idx < 64 * 64; idx += 256) {
        int u = idx >> 6, k4 = idx & 63;
        float4 v = *(const float4*)&w1[u * 256 + k4 * 4];
        __half2* d = (__half2*)&Bh[u * 264 + k4 * 4];
        d[0] = __floats2half2_rn(v.x, v.y);
        d[1] = __floats2half2_rn(v.z, v.w);
    }
    __syncthreads();

    // GEMM1: warp (mt, nq): rows mt*16..+15, cols nq*16..+15
    const int mt = wid & 1;
    const int nq = wid >> 1;
    const int g  = lane >> 2;
    const int tl = lane & 3;
    const unsigned abase = sbh + H_AH +
        (unsigned)((mt * 16 + (lane & 7) + 8 * ((lane >> 3) & 1)) * 528 + (lane >> 4) * 16);
    const unsigned bbase = sbh + H_BH +
        (unsigned)((nq * 16 + (lane & 7) + 8 * (lane >> 4)) * 528 + ((lane >> 3) & 1) * 16);

    float acc[8];
    #pragma unroll
    for (int i = 0; i < 8; ++i) acc[i] = 0.f;

    #pragma unroll
    for (int kc = 0; kc < 16; ++kc) {
        unsigned a0, a1, a2, a3, b0, b1, b2, b3;
        ldsm_x4(abase + kc * 32, a0, a1, a2, a3);
        ldsm_x4(bbase + kc * 32, b0, b1, b2, b3);
        mma16816(acc[0], acc[1], acc[2], acc[3], a0, a1, a2, a3, b0, b1);
        mma16816(acc[4], acc[5], acc[6], acc[7], a0, a1, a2, a3, b2, b3);
    }

    // relu + bias -> qb
    const int r0h = mt * 16 + g;
    const int r1h = r0h + 8;
    #pragma unroll
    for (int nt = 0; nt < 2; ++nt) {
        int col = nq * 16 + nt * 8 + tl * 2;
        float bb0 = b1[col], bb1 = b1[col + 1];
        qb[r0h * 66 + col]     = fmaxf(acc[nt * 4 + 0] + bb0, 0.f);
        qb[r0h * 66 + col + 1] = fmaxf(acc[nt * 4 + 1] + bb1, 0.f);
        qb[r1h * 66 + col]     = fmaxf(acc[nt * 4 + 2] + bb0, 0.f);
        qb[r1h * 66 + col + 1] = fmaxf(acc[nt * 4 + 3] + bb1, 0.f);
    }
    __syncthreads();

    // GEMV2: 32 rows x 6 outputs
    if (tid < 32 * AA) {
        int r = tid / AA;
        int a = tid - r * AA;
        float acc2 = b2[a];
        #pragma unroll 8
        for (int k = 0; k < 64; ++k)
            acc2 = fmaf(w2[a * 64 + k], qb[r * 66 + k], acc2);
        if (br == 0) out[(row0 + r) * AA + a] = acc2;        // q (no relu)
        else         ib[r * 8 + a] = fmaxf(acc2, 0.f);       // i vec
    }
    if (br == 1) {
        __syncthreads();
        if (tid < 32) {
            int r = tid;
            float m = ib[r * 8];
            #pragma unroll
            for (int j = 1; j < AA; ++j) m = fmaxf(m, ib[r * 8 + j]);
            float s = 0.f;
            #pragma unroll
            for (int j = 0; j < AA; ++j) s += __expf(ib[r * 8 + j] - m);
            float lse = m + __logf(s);
            #pragma unroll
            for (int j = 0; j < AA; ++j) {
                float iv = ib[r * 8 + j];
                out[BB * AA + (row0 + r) * AA + j]     = iv - lse;
                out[2 * BB * AA + (row0 + r) * AA + j] = iv;
            }
        }
    }
}

extern "C" void kernel_launch(void* const* d_in, const int* in_sizes, int n_in,
                              void* d_out, int out_size)
{
    const float* x0 = (const float*)d_in[0];
    const float* x1 = (const float*)d_in[1];
    const float* x2 = (const float*)d_in[2];
    const float* s2 = (const float*)d_in[3];
    const float* q00_wih = (const float*)d_in[4];
    const float* q00_whh = (const float*)d_in[5];
    const float* q00_b   = (const float*)d_in[6];
    const float* q01_wih = (const float*)d_in[7];
    const float* q01_whh = (const float*)d_in[8];
    const float* q01_b   = (const float*)d_in[9];
    const float* i00_wih = (const float*)d_in[10];
    const float* i00_whh = (const float*)d_in[11];
    const float* i00_b   = (const float*)d_in[12];
    const float* i01_wih = (const float*)d_in[13];
    const float* i01_whh = (const float*)d_in[14];
    const float* i01_b   = (const float*)d_in[15];
    const float* i02_wih = (const float*)d_in[16];
    const float* i02_whh = (const float*)d_in[17];
    const float* i02_b   = (const float*)d_in[18];
    const float* q03_w = (const float*)d_in[19];
    const float* q03_b = (const float*)d_in[20];
    const float* q1_w  = (const float*)d_in[21];
    const float* q1_b  = (const float*)d_in[22];
    const float* q2_w  = (const float*)d_in[23];
    const float* q2_b  = (const float*)d_in[24];
    const float* i03_w = (const float*)d_in[25];
    const float* i03_b = (const float*)d_in[26];
    const float* i1_w  = (const float*)d_in[27];
    const float* i1_b  = (const float*)d_in[28];
    const float* i2_w  = (const float*)d_in[29];
    const float* i2_b  = (const float*)d_in[30];
    float* out = (float*)d_out;

    cudaFuncSetAttribute(lstm_mma_kernel, cudaFuncAttributeMaxDynamicSharedMemorySize, LSTM_SMEM_BYTES);
    cudaFuncSetAttribute(head_kernel, cudaFuncAttributeMaxDynamicSharedMemorySize, HEAD_SMEM_BYTES);

    dim3 grid(BB / MROWS, 6);   // 128 batch tiles x 6 LSTM runs = 768 CTAs, 2/SM
    lstm_mma_kernel<<<grid, 256, LSTM_SMEM_BYTES>>>(
        x0, x1, x2,
        q00_wih, q00_whh, q00_b,
        q01_wih, q01_whh, q01_b,
        i00_wih, i00_whh, i00_b,
        i01_wih, i01_whh, i01_b,
        i02_wih, i02_whh, i02_b);

    head_kernel<<<dim3(BB / 32, 2), 256, HEAD_SMEM_BYTES>>>(
        s2,
        q03_w, q03_b, q1_w, q1_b, q2_w, q2_b,
        i03_w, i03_b, i1_w, i1_b, i2_w, i2_b,
        out);
}